// round 5
// baseline (speedup 1.0000x reference)
#include <cuda_runtime.h>
#include <math.h>

// Attention4DDownsample — fused, one CTA per image.
// KV GEMM: SMEM-staged outer-product with f32x2 pos-pair accumulators.

#define THREADS 512
#define NWARP   16
#define EPS     1e-5f
#define SCALE   0.25f

// shared layout (float offsets)
#define OFF_XS    0        // xs[c][50], 384x50, col 49 zeroed  (19200)
#define OFF_WBUF  19200    // 2 x (4 x 644) weight chunk buffers (5152)
#define WS        644
#define WBUFSZ    2576
#define OFF_KSM   24352    // k_out[128][49]                    (6272)
#define OFF_V     30624    // v_out[512][49]                    (25088)
#define OFF_QO    55712    // q_out[128][16]                    (2048)
#define OFF_ST    24352    // sT[16][390] overlay (pre-P4)      (6240)
#define SST       390
#define OFF_PROBS 0        // probs[128][52] overlay (post-P4)  (6656)
#define PRS       52
#define OFF_PRE   6656     // preT[16][518] overlay             (8288)
#define PRE       518
#define SM_FLOATS 57760    // 231,040 bytes

typedef unsigned long long ull;

__device__ __forceinline__ ull fma2(ull a, ull b, ull c) {
    ull d;
    asm("fma.rn.f32x2 %0, %1, %2, %3;" : "=l"(d) : "l"(a), "l"(b), "l"(c));
    return d;
}
__device__ __forceinline__ ull pack2(float v) {
    ull d;
    asm("mov.b64 %0, {%1,%1};" : "=l"(d) : "f"(v));
    return d;
}
__device__ __forceinline__ float psum(ull v) {
    float a, b;
    asm("mov.b64 {%0,%1}, %2;" : "=f"(a), "=f"(b) : "l"(v));
    return a + b;
}
__device__ __forceinline__ void unpack2(ull v, float& a, float& b) {
    asm("mov.b64 {%0,%1}, %2;" : "=f"(a), "=f"(b) : "l"(v));
}
__device__ __forceinline__ ull lds_u64(const float* p) { return *(const ull*)p; }

__global__ __launch_bounds__(THREADS, 1)
void attn4dds_kernel(
    const float* __restrict__ x,
    const float* __restrict__ qlw, const float* __restrict__ qlb,
    const float* __restrict__ qpw, const float* __restrict__ qpb, const float* __restrict__ qbn,
    const float* __restrict__ kw,  const float* __restrict__ kb,  const float* __restrict__ kbn,
    const float* __restrict__ vw,  const float* __restrict__ vb,  const float* __restrict__ vbn,
    const float* __restrict__ vlw, const float* __restrict__ vlb, const float* __restrict__ vlbn,
    const float* __restrict__ pw,  const float* __restrict__ pb,  const float* __restrict__ pbn,
    const float* __restrict__ ab,  const int* __restrict__ bidx_g, int n_off,
    float* __restrict__ out)
{
    extern __shared__ float sm[];
    const int tid  = threadIdx.x;
    const int lane = tid & 31;
    const int wid  = tid >> 5;
    const int b    = blockIdx.x;

    // ---------- P1: stage x[b] into xs[c][50] (col 49 zeroed) ----------
    {
        const float* xin = x + (size_t)b * 18816;
        for (int i = tid; i < 18816; i += THREADS) {
            const int c = i / 49;
            const int p = i - c * 49;
            sm[OFF_XS + c * 50 + p] = xin[i];
        }
        if (tid < 384) sm[OFF_XS + tid * 50 + 49] = 0.f;
    }
    __syncthreads();

    // ---------- P2: sT[p][c] = dw3x3s2(x)+qlb + avgpool ----------
    if (tid < 384) {
        const int c = tid;
        const float* xc = sm + OFF_XS + c * 50;
        float w9[9];
        #pragma unroll
        for (int i = 0; i < 9; i++) w9[i] = __ldg(&qlw[c * 9 + i]);
        const float bq = __ldg(&qlb[c]);
        #pragma unroll
        for (int i = 0; i < 4; i++) {
            #pragma unroll
            for (int j = 0; j < 4; j++) {
                float acc = bq;
                #pragma unroll
                for (int ki = 0; ki < 3; ki++) {
                    const int r = 2 * i - 1 + ki;
                    if (r < 0 || r > 6) continue;
                    #pragma unroll
                    for (int kj = 0; kj < 3; kj++) {
                        const int cl = 2 * j - 1 + kj;
                        if (cl < 0 || cl > 6) continue;
                        acc += w9[ki * 3 + kj] * xc[r * 7 + cl];
                    }
                }
                if (i < 3 && j < 3) {
                    acc += 0.25f * (xc[(2*i)*7 + 2*j]   + xc[(2*i)*7 + 2*j+1] +
                                    xc[(2*i+1)*7 + 2*j] + xc[(2*i+1)*7 + 2*j+1]);
                }
                sm[OFF_ST + (i * 4 + j) * SST + c] = acc;
            }
        }
    }
    __syncthreads();

    // ---------- P3: q GEMM  qo[128][16] ----------
    {
        const int p   = lane & 15;
        const int sub = lane >> 4;
        const int oc0 = wid * 8;
        ull acc[8];
        #pragma unroll
        for (int r = 0; r < 8; r++) acc[r] = 0ULL;
        #pragma unroll 2
        for (int c8 = 0; c8 < 48; c8++) {
            const int kofs = 8 * c8 + 4 * sub;
            const ull a0 = lds_u64(&sm[OFF_ST + p * SST + kofs]);
            const ull a1 = lds_u64(&sm[OFF_ST + p * SST + kofs + 2]);
            #pragma unroll
            for (int r = 0; r < 8; r++) {
                const ulonglong2 w = __ldg((const ulonglong2*)(qpw + (oc0 + r) * 384 + kofs));
                acc[r] = fma2(w.x, a0, acc[r]);
                acc[r] = fma2(w.y, a1, acc[r]);
            }
        }
        #pragma unroll
        for (int r = 0; r < 8; r++) {
            float s = psum(acc[r]);
            s += __shfl_xor_sync(0xffffffffu, s, 16);
            if (sub == 0) {
                const int oc = oc0 + r;
                const float ga = __ldg(&qbn[oc]),       be = __ldg(&qbn[128 + oc]);
                const float mn = __ldg(&qbn[256 + oc]), vr = __ldg(&qbn[384 + oc]);
                const float aa = ga * rsqrtf(vr + EPS);
                sm[OFF_QO + oc * 16 + p] = (s + __ldg(&qpb[oc])) * aa + (be - mn * aa);
            }
        }
    }
    __syncthreads();

    // ---------- P4: kv GEMM (640 x 49, K=384), staged outer-product ----------
    {
        const int og  = lane >> 2;            // 0..7
        const int pg  = lane & 3;             // 0..3
        const int oc0 = wid * 40 + og * 5;    // 5 output channels per thread
        ull acc[5][7];
        #pragma unroll
        for (int r = 0; r < 5; r++)
            #pragma unroll
            for (int s = 0; s < 7; s++) acc[r][s] = 0ULL;

        float4 pfa, pfb;
        // prefetch chunk 0
        {
            const float* src = (tid < 128) ? (kw + tid * 384) : (vw + (tid - 128) * 384);
            pfa = __ldg((const float4*)src);
            if (tid < 128) pfb = __ldg((const float4*)(vw + (384 + tid) * 384));
        }
        #pragma unroll 1
        for (int ch = 0; ch < 96; ch++) {
            float* wb = sm + OFF_WBUF + (ch & 1) * WBUFSZ;
            wb[0 * WS + tid] = pfa.x;
            wb[1 * WS + tid] = pfa.y;
            wb[2 * WS + tid] = pfa.z;
            wb[3 * WS + tid] = pfa.w;
            if (tid < 128) {
                wb[0 * WS + 512 + tid] = pfb.x;
                wb[1 * WS + 512 + tid] = pfb.y;
                wb[2 * WS + 512 + tid] = pfb.z;
                wb[3 * WS + 512 + tid] = pfb.w;
            }
            __syncthreads();
            if (ch < 95) {
                const int k0 = (ch + 1) * 4;
                const float* src = (tid < 128) ? (kw + tid * 384 + k0)
                                               : (vw + (tid - 128) * 384 + k0);
                pfa = __ldg((const float4*)src);
                if (tid < 128) pfb = __ldg((const float4*)(vw + (384 + tid) * 384 + k0));
            }
            #pragma unroll
            for (int kk = 0; kk < 4; kk++) {
                const float* wr = wb + kk * WS;
                const float* xr = sm + OFF_XS + (ch * 4 + kk) * 50;
                ull wp[5];
                #pragma unroll
                for (int r = 0; r < 5; r++) wp[r] = pack2(wr[oc0 + r]);
                #pragma unroll
                for (int s = 0; s < 7; s++) {
                    const int pp = 4 * s + pg;            // pairs 0..27; 25..27 waste
                    const ull a = lds_u64(xr + 2 * pp);
                    #pragma unroll
                    for (int r = 0; r < 5; r++) acc[r][s] = fma2(wp[r], a, acc[r][s]);
                }
            }
        }
        // epilogue: BN + store to ksm / v
        #pragma unroll
        for (int r = 0; r < 5; r++) {
            const int oc = oc0 + r;
            float aa, sh, bs;
            int base;
            if (oc < 128) {
                const float ga = __ldg(&kbn[oc]),       be = __ldg(&kbn[128 + oc]);
                const float mn = __ldg(&kbn[256 + oc]), vr = __ldg(&kbn[384 + oc]);
                aa = ga * rsqrtf(vr + EPS); sh = be - mn * aa; bs = __ldg(&kb[oc]);
                base = OFF_KSM + oc * 49;
            } else {
                const int rr = oc - 128;
                const float ga = __ldg(&vbn[rr]),        be = __ldg(&vbn[512 + rr]);
                const float mn = __ldg(&vbn[1024 + rr]), vr = __ldg(&vbn[1536 + rr]);
                aa = ga * rsqrtf(vr + EPS); sh = be - mn * aa; bs = __ldg(&vb[rr]);
                base = OFF_V + rr * 49;
            }
            #pragma unroll
            for (int s = 0; s < 7; s++) {
                const int pp = 4 * s + pg;
                if (pp > 24) continue;
                float lo, hi;
                unpack2(acc[r][s], lo, hi);
                sm[base + 2 * pp] = (lo + bs) * aa + sh;
                if (pp < 24) sm[base + 2 * pp + 1] = (hi + bs) * aa + sh;
            }
        }
    }
    __syncthreads();

    // ---------- P5: attention scores + softmax -> probs[128][52] ----------
    {
        for (int row = wid; row < 128; row += NWARP) {
            const int h = row >> 4, q = row & 15;
            float qv[16];
            #pragma unroll
            for (int kd = 0; kd < 16; kd++) qv[kd] = sm[OFF_QO + (h * 16 + kd) * 16 + q];
            float a0 = 0.f, a1 = 0.f;
            #pragma unroll
            for (int kd = 0; kd < 16; kd++) {
                const float* kr = sm + OFF_KSM + (h * 16 + kd) * 49;
                a0 += qv[kd] * kr[lane];
                if (lane < 17) a1 += qv[kd] * kr[lane + 32];
            }
            a0 = a0 * SCALE + __ldg(&ab[h * n_off + __ldg(&bidx_g[q * 49 + lane])]);
            if (lane < 17) a1 = a1 * SCALE + __ldg(&ab[h * n_off + __ldg(&bidx_g[q * 49 + lane + 32])]);
            else           a1 = -1e30f;
            float m = fmaxf(a0, a1);
            #pragma unroll
            for (int o = 16; o > 0; o >>= 1) m = fmaxf(m, __shfl_xor_sync(0xffffffffu, m, o));
            const float e0 = __expf(a0 - m);
            const float e1 = (lane < 17) ? __expf(a1 - m) : 0.f;
            float ss = e0 + e1;
            #pragma unroll
            for (int o = 16; o > 0; o >>= 1) ss += __shfl_xor_sync(0xffffffffu, ss, o);
            const float inv = 1.f / ss;
            sm[OFF_PROBS + row * PRS + lane] = e0 * inv;
            if (lane < 17) sm[OFF_PROBS + row * PRS + lane + 32] = e1 * inv;
        }
    }
    __syncthreads();

    // ---------- P5b: preT[p][c] = relu(attn@v + BN(v_local)) ----------
    {
        const int c = tid;                 // 512 channels
        const int h = c >> 6;
        const float* vr_ = sm + OFF_V + c * 49;
        float acc[16];
        #pragma unroll
        for (int p = 0; p < 16; p++) acc[p] = 0.f;
        #pragma unroll 2
        for (int k4 = 0; k4 < 12; k4++) {
            const float v0 = vr_[4 * k4 + 0];
            const float v1 = vr_[4 * k4 + 1];
            const float v2 = vr_[4 * k4 + 2];
            const float v3 = vr_[4 * k4 + 3];
            #pragma unroll
            for (int p = 0; p < 16; p++) {
                const float4 pr = *(const float4*)&sm[OFF_PROBS + (h * 16 + p) * PRS + 4 * k4];
                acc[p] += pr.x * v0 + pr.y * v1 + pr.z * v2 + pr.w * v3;
            }
        }
        {
            const float v48 = vr_[48];
            #pragma unroll
            for (int p = 0; p < 16; p++)
                acc[p] += sm[OFF_PROBS + (h * 16 + p) * PRS + 48] * v48;
        }
        float w9[9];
        #pragma unroll
        for (int i = 0; i < 9; i++) w9[i] = __ldg(&vlw[c * 9 + i]);
        const float bl = __ldg(&vlb[c]);
        const float ga = __ldg(&vlbn[c]),        be = __ldg(&vlbn[512 + c]);
        const float mn = __ldg(&vlbn[1024 + c]), vr2 = __ldg(&vlbn[1536 + c]);
        const float aa = ga * rsqrtf(vr2 + EPS);
        const float sh = be - mn * aa;
        #pragma unroll
        for (int i = 0; i < 4; i++) {
            #pragma unroll
            for (int j = 0; j < 4; j++) {
                float vl = bl;
                #pragma unroll
                for (int ki = 0; ki < 3; ki++) {
                    const int r = 2 * i - 1 + ki;
                    if (r < 0 || r > 6) continue;
                    #pragma unroll
                    for (int kj = 0; kj < 3; kj++) {
                        const int cl = 2 * j - 1 + kj;
                        if (cl < 0 || cl > 6) continue;
                        vl += w9[ki * 3 + kj] * vr_[r * 7 + cl];
                    }
                }
                const int p = i * 4 + j;
                sm[OFF_PRE + p * PRE + c] = fmaxf(acc[p] + vl * aa + sh, 0.f);
            }
        }
    }
    __syncthreads();

    // ---------- P6: proj GEMM  out[384][16] ----------
    {
        const int p   = lane & 15;
        const int sub = lane >> 4;
        float* ob = out + (size_t)b * 6144;
        #pragma unroll 1
        for (int g = 0; g < 3; g++) {
            const int oc0 = (g * 16 + wid) * 8;
            ull acc[8];
            #pragma unroll
            for (int r = 0; r < 8; r++) acc[r] = 0ULL;
            #pragma unroll 2
            for (int c8 = 0; c8 < 64; c8++) {
                const int kofs = 8 * c8 + 4 * sub;
                const ull a0 = lds_u64(&sm[OFF_PRE + p * PRE + kofs]);
                const ull a1 = lds_u64(&sm[OFF_PRE + p * PRE + kofs + 2]);
                #pragma unroll
                for (int r = 0; r < 8; r++) {
                    const ulonglong2 w = __ldg((const ulonglong2*)(pw + (oc0 + r) * 512 + kofs));
                    acc[r] = fma2(w.x, a0, acc[r]);
                    acc[r] = fma2(w.y, a1, acc[r]);
                }
            }
            #pragma unroll
            for (int r = 0; r < 8; r++) {
                float s = psum(acc[r]);
                s += __shfl_xor_sync(0xffffffffu, s, 16);
                if (sub == 0) {
                    const int oc = oc0 + r;
                    const float ga = __ldg(&pbn[oc]),       be = __ldg(&pbn[384 + oc]);
                    const float mn = __ldg(&pbn[768 + oc]), vr = __ldg(&pbn[1152 + oc]);
                    const float aa = ga * rsqrtf(vr + EPS);
                    ob[oc * 16 + p] = (s + __ldg(&pb[oc])) * aa + (be - mn * aa);
                }
            }
        }
    }
}

extern "C" void kernel_launch(void* const* d_in, const int* in_sizes, int n_in,
                              void* d_out, int out_size)
{
    const float* x    = (const float*)d_in[0];
    const float* qlw  = (const float*)d_in[1];
    const float* qlb  = (const float*)d_in[2];
    const float* qpw  = (const float*)d_in[3];
    const float* qpb  = (const float*)d_in[4];
    const float* qbn  = (const float*)d_in[5];
    const float* kw   = (const float*)d_in[6];
    const float* kb   = (const float*)d_in[7];
    const float* kbn  = (const float*)d_in[8];
    const float* vw   = (const float*)d_in[9];
    const float* vb   = (const float*)d_in[10];
    const float* vbn  = (const float*)d_in[11];
    const float* vlw  = (const float*)d_in[12];
    const float* vlb  = (const float*)d_in[13];
    const float* vlbn = (const float*)d_in[14];
    const float* pw   = (const float*)d_in[15];
    const float* pb   = (const float*)d_in[16];
    const float* pbn  = (const float*)d_in[17];
    const float* ab   = (const float*)d_in[18];
    const int*   bidx = (const int*)d_in[19];

    const int Bsz   = in_sizes[0] / (384 * 49);
    const int n_off = in_sizes[18] / 8;
    const size_t smem = (size_t)SM_FLOATS * sizeof(float);

    cudaFuncSetAttribute(attn4dds_kernel,
                         cudaFuncAttributeMaxDynamicSharedMemorySize, (int)smem);

    attn4dds_kernel<<<Bsz, THREADS, smem>>>(
        x, qlw, qlb, qpw, qpb, qbn, kw, kb, kbn, vw, vb, vbn,
        vlw, vlb, vlbn, pw, pb, pbn, ab, bidx, n_off, (float*)d_out);
}

// round 7
// speedup vs baseline: 4.3840x; 4.3840x over previous
#include <cuda_runtime.h>
#include <math.h>
#include <stdint.h>

// Attention4DDownsample — fused, one CTA per image; big GEMMs via mma.sync tf32.
// B=2048, DIM=384, N=49(pad 56), N2=16, HEADS=8, KEY_DIM=16, D=64, NH_KD=128, DH=512.

#define THREADS 640
#define NWARP   20
#define EPS     1e-5f
#define SCALE   0.25f

// ---- SMEM layout (float offsets) ----
#define OFF_XS    0        // xs[384][56] tf32-rounded, cols 49..55 zero   (21504)
#define XSS       56
#define OFF_AB    21504    // KV A-chunk: 8 x 648                          (5184)
#define ABS       648
#define OFF_ST    31872    // sT[16][390]                                  (6240)
#define SST       390
#define OFF_QO    51584    // qo[128][16]                                  (2048) -> 53632
// overlays after KV mma (xs/abuf dead):
#define OFF_KS    0        // k[128][51]                                   (6528)
#define KSS       51
#define OFF_V     6528     // v[512][51]                                   (26112) -> 32640
#define OFF_PROBS 32640    // probs[128][52]                               (6656)  -> 39296
#define PRS       52
#define OFF_PRE   39296    // pre[512][24]                                 (12288) -> 51584
#define PRES      24
#define OFF_AB2   0        // proj A-chunk: 8 x 392 (over dead k)          (3136)
#define AB2S      392
#define SM_FLOATS 53632    // 214,528 bytes

// weight scratch (transposed, tf32-rounded) — static device arrays (no alloc)
__device__ float g_wT[384 * 640];    // [k][oc], oc<128 = K-branch, else V
__device__ float g_pwT[512 * 384];   // [k][oc]

__device__ __forceinline__ float totf32(float f) {
    uint32_t r;
    asm("cvt.rna.tf32.f32 %0, %1;" : "=r"(r) : "f"(f));
    return __uint_as_float(r);
}
__device__ __forceinline__ void mma8(float* d, uint32_t a0, uint32_t a1, uint32_t a2,
                                     uint32_t a3, uint32_t b0, uint32_t b1) {
    asm("mma.sync.aligned.m16n8k8.row.col.f32.tf32.tf32.f32 "
        "{%0,%1,%2,%3}, {%4,%5,%6,%7}, {%8,%9}, {%0,%1,%2,%3};"
        : "+f"(d[0]), "+f"(d[1]), "+f"(d[2]), "+f"(d[3])
        : "r"(a0), "r"(a1), "r"(a2), "r"(a3), "r"(b0), "r"(b1));
}
typedef unsigned long long ull;
__device__ __forceinline__ ull fma2(ull a, ull b, ull c) {
    ull d;
    asm("fma.rn.f32x2 %0, %1, %2, %3;" : "=l"(d) : "l"(a), "l"(b), "l"(c));
    return d;
}
__device__ __forceinline__ float psum(ull v) {
    float a, b;
    asm("mov.b64 {%0,%1}, %2;" : "=f"(a), "=f"(b) : "l"(v));
    return a + b;
}
__device__ __forceinline__ ull lds_u64(const float* p) { return *(const ull*)p; }

// ---- pre-pass: transpose + tf32-round weights ----
__global__ void transpose_w_kernel(const float* __restrict__ kw,
                                   const float* __restrict__ vw,
                                   const float* __restrict__ pw) {
    int i = blockIdx.x * blockDim.x + threadIdx.x;
    if (i < 384 * 640) {
        const int k = i / 640, oc = i % 640;
        const float v = (oc < 128) ? kw[oc * 384 + k] : vw[(oc - 128) * 384 + k];
        g_wT[i] = totf32(v);
    } else {
        const int j = i - 384 * 640;
        if (j < 512 * 384) {
            const int k = j / 384, oc = j % 384;
            g_pwT[j] = totf32(pw[oc * 512 + k]);
        }
    }
}

__global__ __launch_bounds__(THREADS, 1)
void attn4dds_kernel(
    const float* __restrict__ x,
    const float* __restrict__ qlw, const float* __restrict__ qlb,
    const float* __restrict__ qpw, const float* __restrict__ qpb, const float* __restrict__ qbn,
    const float* __restrict__ kw,  const float* __restrict__ kb,  const float* __restrict__ kbn,
    const float* __restrict__ vw,  const float* __restrict__ vb,  const float* __restrict__ vbn,
    const float* __restrict__ vlw, const float* __restrict__ vlb, const float* __restrict__ vlbn,
    const float* __restrict__ pw,  const float* __restrict__ pb,  const float* __restrict__ pbn,
    const float* __restrict__ ab,  const int* __restrict__ bidx_g, int n_off,
    float* __restrict__ out)
{
    extern __shared__ float sm[];
    const int tid  = threadIdx.x;
    const int lane = tid & 31;
    const int wid  = tid >> 5;
    const int b    = blockIdx.x;
    const int tq   = lane & 3;     // mma quad col
    const int tr   = lane >> 2;    // mma row-in-group

    // ---------- P1: stage x[b] -> xs[c][56] tf32, zero pad cols ----------
    {
        for (int i = tid; i < 384 * 7; i += THREADS)
            sm[OFF_XS + (i / 7) * XSS + 49 + (i % 7)] = 0.f;
        const float* xin = x + (size_t)b * 18816;
        for (int i = tid; i < 18816; i += THREADS) {
            const int c = i / 49, p = i - c * 49;
            sm[OFF_XS + c * XSS + p] = totf32(xin[i]);
        }
    }
    __syncthreads();

    // ---------- P2: sT[p][c] = dw3x3s2(x)+qlb + avgpool ----------
    if (tid < 384) {
        const int c = tid;
        const float* xc = sm + OFF_XS + c * XSS;
        float w9[9];
        #pragma unroll
        for (int i = 0; i < 9; i++) w9[i] = __ldg(&qlw[c * 9 + i]);
        const float bq = __ldg(&qlb[c]);
        #pragma unroll
        for (int i = 0; i < 4; i++) {
            #pragma unroll
            for (int j = 0; j < 4; j++) {
                float acc = bq;
                #pragma unroll
                for (int ki = 0; ki < 3; ki++) {
                    const int r = 2 * i - 1 + ki;
                    if (r < 0 || r > 6) continue;
                    #pragma unroll
                    for (int kj = 0; kj < 3; kj++) {
                        const int cl = 2 * j - 1 + kj;
                        if (cl < 0 || cl > 6) continue;
                        acc += w9[ki * 3 + kj] * xc[r * 7 + cl];
                    }
                }
                if (i < 3 && j < 3) {
                    acc += 0.25f * (xc[(2*i)*7 + 2*j]   + xc[(2*i)*7 + 2*j+1] +
                                    xc[(2*i+1)*7 + 2*j] + xc[(2*i+1)*7 + 2*j+1]);
                }
                sm[OFF_ST + (i * 4 + j) * SST + c] = acc;
            }
        }
    }
    __syncthreads();

    // ---------- P3: q GEMM (scalar fp32 FFMA2)  qo[128][16] ----------
    if (wid < 16) {
        const int p   = lane & 15;
        const int sub = lane >> 4;
        const int oc0 = wid * 8;
        ull acc[8];
        #pragma unroll
        for (int r = 0; r < 8; r++) acc[r] = 0ULL;
        #pragma unroll 2
        for (int c8 = 0; c8 < 48; c8++) {
            const int kofs = 8 * c8 + 4 * sub;
            const ull a0 = lds_u64(&sm[OFF_ST + p * SST + kofs]);
            const ull a1 = lds_u64(&sm[OFF_ST + p * SST + kofs + 2]);
            #pragma unroll
            for (int r = 0; r < 8; r++) {
                const ulonglong2 w = __ldg((const ulonglong2*)(qpw + (oc0 + r) * 384 + kofs));
                acc[r] = fma2(w.x, a0, acc[r]);
                acc[r] = fma2(w.y, a1, acc[r]);
            }
        }
        #pragma unroll
        for (int r = 0; r < 8; r++) {
            float s = psum(acc[r]);
            s += __shfl_xor_sync(0xffffffffu, s, 16);
            if (sub == 0) {
                const int oc = oc0 + r;
                const float ga = __ldg(&qbn[oc]),       be = __ldg(&qbn[128 + oc]);
                const float mn = __ldg(&qbn[256 + oc]), vr = __ldg(&qbn[384 + oc]);
                const float aa = ga * rsqrtf(vr + EPS);
                sm[OFF_QO + oc * 16 + p] = (s + __ldg(&qpb[oc])) * aa + (be - mn * aa);
            }
        }
    }
    __syncthreads();

    // ---------- P4: KV GEMM via mma.sync tf32: D[640][56] = wT^T @ xs ----------
    float acc[2][7][4];
    #pragma unroll
    for (int j = 0; j < 2; j++)
        #pragma unroll
        for (int nt = 0; nt < 7; nt++)
            #pragma unroll
            for (int e = 0; e < 4; e++) acc[j][nt][e] = 0.f;
    {
        float* abf = sm + OFF_AB;
        float4 pf[2];
        #pragma unroll
        for (int u = 0; u < 2; u++) {
            const int idx = tid + u * 640;
            const int kk = idx / 160, c4 = idx % 160;
            pf[u] = *(const float4*)&g_wT[kk * 640 + c4 * 4];
        }
        #pragma unroll 1
        for (int ch = 0; ch < 48; ch++) {
            #pragma unroll
            for (int u = 0; u < 2; u++) {
                const int idx = tid + u * 640;
                const int kk = idx / 160, c4 = idx % 160;
                *(float4*)&abf[kk * ABS + c4 * 4] = pf[u];
            }
            __syncthreads();
            if (ch < 47) {
                #pragma unroll
                for (int u = 0; u < 2; u++) {
                    const int idx = tid + u * 640;
                    const int kk = idx / 160, c4 = idx % 160;
                    pf[u] = *(const float4*)&g_wT[((ch + 1) * 8 + kk) * 640 + c4 * 4];
                }
            }
            // B fragments from xs (shared across this warp's m-tiles)
            uint32_t bf[7][2];
            const int kg = ch * 8;
            #pragma unroll
            for (int nt = 0; nt < 7; nt++) {
                bf[nt][0] = __float_as_uint(sm[OFF_XS + (kg + tq) * XSS + nt * 8 + tr]);
                bf[nt][1] = __float_as_uint(sm[OFF_XS + (kg + 4 + tq) * XSS + nt * 8 + tr]);
            }
            #pragma unroll
            for (int j = 0; j < 2; j++) {
                const int m0 = (wid * 2 + j) * 16;
                const uint32_t a0 = __float_as_uint(abf[tq * ABS + m0 + tr]);
                const uint32_t a1 = __float_as_uint(abf[tq * ABS + m0 + 8 + tr]);
                const uint32_t a2 = __float_as_uint(abf[(tq + 4) * ABS + m0 + tr]);
                const uint32_t a3 = __float_as_uint(abf[(tq + 4) * ABS + m0 + 8 + tr]);
                #pragma unroll
                for (int nt = 0; nt < 7; nt++)
                    mma8(acc[j][nt], a0, a1, a2, a3, bf[nt][0], bf[nt][1]);
            }
            __syncthreads();
        }
    }
    // ---- KV epilogue: BN + store k[128][51] / v[512][51] (xs/abuf dead) ----
    {
        #pragma unroll
        for (int j = 0; j < 2; j++) {
            const int mt = wid * 2 + j;
            #pragma unroll
            for (int rh = 0; rh < 2; rh++) {
                const int oc = mt * 16 + tr + rh * 8;
                float aa, sh, bs;
                float* dst;
                if (oc < 128) {
                    const float ga = __ldg(&kbn[oc]),       be = __ldg(&kbn[128 + oc]);
                    const float mn = __ldg(&kbn[256 + oc]), vr = __ldg(&kbn[384 + oc]);
                    aa = ga * rsqrtf(vr + EPS); sh = be - mn * aa; bs = __ldg(&kb[oc]);
                    dst = sm + OFF_KS + oc * KSS;
                } else {
                    const int vc = oc - 128;
                    const float ga = __ldg(&vbn[vc]),        be = __ldg(&vbn[512 + vc]);
                    const float mn = __ldg(&vbn[1024 + vc]), vr = __ldg(&vbn[1536 + vc]);
                    aa = ga * rsqrtf(vr + EPS); sh = be - mn * aa; bs = __ldg(&vb[vc]);
                    dst = sm + OFF_V + vc * KSS;
                }
                #pragma unroll
                for (int nt = 0; nt < 7; nt++) {
                    const int pos = nt * 8 + 2 * tq;
                    const float v0 = acc[j][nt][rh * 2 + 0];
                    const float v1 = acc[j][nt][rh * 2 + 1];
                    if (pos < 49)     dst[pos]     = (v0 + bs) * aa + sh;
                    if (pos + 1 < 49) dst[pos + 1] = (v1 + bs) * aa + sh;
                }
            }
        }
    }
    __syncthreads();

    // ---------- P5: attention scores + softmax -> probs[128][52] ----------
    {
        for (int row = wid; row < 128; row += NWARP) {
            const int h = row >> 4, q = row & 15;
            float qv[16];
            #pragma unroll
            for (int kd = 0; kd < 16; kd++) qv[kd] = sm[OFF_QO + (h * 16 + kd) * 16 + q];
            float a0 = 0.f, a1 = 0.f;
            #pragma unroll
            for (int kd = 0; kd < 16; kd++) {
                const float* kr = sm + OFF_KS + (h * 16 + kd) * KSS;
                a0 += qv[kd] * kr[lane];
                if (lane < 17) a1 += qv[kd] * kr[lane + 32];
            }
            a0 = a0 * SCALE + __ldg(&ab[h * n_off + __ldg(&bidx_g[q * 49 + lane])]);
            if (lane < 17) a1 = a1 * SCALE + __ldg(&ab[h * n_off + __ldg(&bidx_g[q * 49 + lane + 32])]);
            else           a1 = -1e30f;
            float m = fmaxf(a0, a1);
            #pragma unroll
            for (int o = 16; o > 0; o >>= 1) m = fmaxf(m, __shfl_xor_sync(0xffffffffu, m, o));
            const float e0 = __expf(a0 - m);
            const float e1 = (lane < 17) ? __expf(a1 - m) : 0.f;
            float ss = e0 + e1;
            #pragma unroll
            for (int o = 16; o > 0; o >>= 1) ss += __shfl_xor_sync(0xffffffffu, ss, o);
            const float inv = 1.f / ss;
            sm[OFF_PROBS + row * PRS + lane] = e0 * inv;
            if (lane < 17) sm[OFF_PROBS + row * PRS + lane + 32] = e1 * inv;
        }
    }
    __syncthreads();

    // ---------- P5b: pre[c][24] = tf32(relu(attn@v + BN(v_local))) ----------
    if (tid < 512) {
        const int c = tid;
        const int h = c >> 6;
        const float* vr_ = sm + OFF_V + c * KSS;
        float pacc[16];
        #pragma unroll
        for (int p = 0; p < 16; p++) pacc[p] = 0.f;
        #pragma unroll 2
        for (int k4 = 0; k4 < 12; k4++) {
            const float v0 = vr_[4 * k4 + 0];
            const float v1 = vr_[4 * k4 + 1];
            const float v2 = vr_[4 * k4 + 2];
            const float v3 = vr_[4 * k4 + 3];
            #pragma unroll
            for (int p = 0; p < 16; p++) {
                const float4 pr = *(const float4*)&sm[OFF_PROBS + (h * 16 + p) * PRS + 4 * k4];
                pacc[p] += pr.x * v0 + pr.y * v1 + pr.z * v2 + pr.w * v3;
            }
        }
        {
            const float v48 = vr_[48];
            #pragma unroll
            for (int p = 0; p < 16; p++)
                pacc[p] += sm[OFF_PROBS + (h * 16 + p) * PRS + 48] * v48;
        }
        float w9[9];
        #pragma unroll
        for (int i = 0; i < 9; i++) w9[i] = __ldg(&vlw[c * 9 + i]);
        const float bl = __ldg(&vlb[c]);
        const float ga = __ldg(&vlbn[c]),        be = __ldg(&vlbn[512 + c]);
        const float mn = __ldg(&vlbn[1024 + c]), vr2 = __ldg(&vlbn[1536 + c]);
        const float aa = ga * rsqrtf(vr2 + EPS);
        const float sh = be - mn * aa;
        #pragma unroll
        for (int i = 0; i < 4; i++) {
            #pragma unroll
            for (int j = 0; j < 4; j++) {
                float vl = bl;
                #pragma unroll
                for (int ki = 0; ki < 3; ki++) {
                    const int r = 2 * i - 1 + ki;
                    if (r < 0 || r > 6) continue;
                    #pragma unroll
                    for (int kj = 0; kj < 3; kj++) {
                        const int cl = 2 * j - 1 + kj;
                        if (cl < 0 || cl > 6) continue;
                        vl += w9[ki * 3 + kj] * vr_[r * 7 + cl];
                    }
                }
                sm[OFF_PRE + c * PRES + i * 4 + j] =
                    totf32(fmaxf(pacc[i * 4 + j] + vl * aa + sh, 0.f));
            }
        }
    }
    __syncthreads();

    // ---------- P6: proj GEMM via mma.sync tf32: D[384][16] = pwT^T @ pre ----------
    {
        float acc2[2][2][4];
        #pragma unroll
        for (int j = 0; j < 2; j++)
            #pragma unroll
            for (int nt = 0; nt < 2; nt++)
                #pragma unroll
                for (int e = 0; e < 4; e++) acc2[j][nt][e] = 0.f;
        float* abf = sm + OFF_AB2;
        float4 pf;
        bool own = (tid < 768 - 640) || true;   // idx guard below
        {
            const int idx = tid;   // 768 float4 per chunk; tid<640 covers idx 0..639, plus second pass
        }
        float4 pf0, pf1; bool h1 = (tid < 128);
        {
            const int i0 = tid, kk0 = i0 / 96, c40 = i0 % 96;
            pf0 = *(const float4*)&g_pwT[kk0 * 384 + c40 * 4];
            if (h1) {
                const int i1 = tid + 640, kk1 = i1 / 96, c41 = i1 % 96;
                pf1 = *(const float4*)&g_pwT[kk1 * 384 + c41 * 4];
            }
        }
        #pragma unroll 1
        for (int ch = 0; ch < 64; ch++) {
            {
                const int i0 = tid, kk0 = i0 / 96, c40 = i0 % 96;
                *(float4*)&abf[kk0 * AB2S + c40 * 4] = pf0;
                if (h1) {
                    const int i1 = tid + 640, kk1 = i1 / 96, c41 = i1 % 96;
                    *(float4*)&abf[kk1 * AB2S + c41 * 4] = pf1;
                }
            }
            __syncthreads();
            if (ch < 63) {
                const int i0 = tid, kk0 = i0 / 96, c40 = i0 % 96;
                pf0 = *(const float4*)&g_pwT[((ch + 1) * 8 + kk0) * 384 + c40 * 4];
                if (h1) {
                    const int i1 = tid + 640, kk1 = i1 / 96, c41 = i1 % 96;
                    pf1 = *(const float4*)&g_pwT[((ch + 1) * 8 + kk1) * 384 + c41 * 4];
                }
            }
            if (wid < 12) {
                const int kg = ch * 8;
                uint32_t bf0[2], bf1[2];
                bf0[0] = __float_as_uint(sm[OFF_PRE + (kg + tq) * PRES + tr]);
                bf0[1] = __float_as_uint(sm[OFF_PRE + (kg + 4 + tq) * PRES + tr]);
                bf1[0] = __float_as_uint(sm[OFF_PRE + (kg + tq) * PRES + 8 + tr]);
                bf1[1] = __float_as_uint(sm[OFF_PRE + (kg + 4 + tq) * PRES + 8 + tr]);
                #pragma unroll
                for (int j = 0; j < 2; j++) {
                    const int m0 = (wid * 2 + j) * 16;
                    const uint32_t a0 = __float_as_uint(abf[tq * AB2S + m0 + tr]);
                    const uint32_t a1 = __float_as_uint(abf[tq * AB2S + m0 + 8 + tr]);
                    const uint32_t a2 = __float_as_uint(abf[(tq + 4) * AB2S + m0 + tr]);
                    const uint32_t a3 = __float_as_uint(abf[(tq + 4) * AB2S + m0 + 8 + tr]);
                    mma8(acc2[j][0], a0, a1, a2, a3, bf0[0], bf0[1]);
                    mma8(acc2[j][1], a0, a1, a2, a3, bf1[0], bf1[1]);
                }
            }
            __syncthreads();
        }
        // proj epilogue: BN -> out
        if (wid < 12) {
            float* ob = out + (size_t)b * 6144;
            #pragma unroll
            for (int j = 0; j < 2; j++) {
                const int mt = wid * 2 + j;
                #pragma unroll
                for (int rh = 0; rh < 2; rh++) {
                    const int oc = mt * 16 + tr + rh * 8;
                    const float ga = __ldg(&pbn[oc]),       be = __ldg(&pbn[384 + oc]);
                    const float mn = __ldg(&pbn[768 + oc]), vr = __ldg(&pbn[1152 + oc]);
                    const float aa = ga * rsqrtf(vr + EPS);
                    const float sh = be - mn * aa, bs = __ldg(&pb[oc]);
                    #pragma unroll
                    for (int nt = 0; nt < 2; nt++) {
                        const int pos = nt * 8 + 2 * tq;
                        ob[oc * 16 + pos]     = (acc2[j][nt][rh * 2 + 0] + bs) * aa + sh;
                        ob[oc * 16 + pos + 1] = (acc2[j][nt][rh * 2 + 1] + bs) * aa + sh;
                    }
                }
            }
        }
    }
}

extern "C" void kernel_launch(void* const* d_in, const int* in_sizes, int n_in,
                              void* d_out, int out_size)
{
    const float* x    = (const float*)d_in[0];
    const float* qlw  = (const float*)d_in[1];
    const float* qlb  = (const float*)d_in[2];
    const float* qpw  = (const float*)d_in[3];
    const float* qpb  = (const float*)d_in[4];
    const float* qbn  = (const float*)d_in[5];
    const float* kw   = (const float*)d_in[6];
    const float* kb   = (const float*)d_in[7];
    const float* kbn  = (const float*)d_in[8];
    const float* vw   = (const float*)d_in[9];
    const float* vb   = (const float*)d_in[10];
    const float* vbn  = (const float*)d_in[11];
    const float* vlw  = (const float*)d_in[12];
    const float* vlb  = (const float*)d_in[13];
    const float* vlbn = (const float*)d_in[14];
    const float* pw   = (const float*)d_in[15];
    const float* pb   = (const float*)d_in[16];
    const float* pbn  = (const float*)d_in[17];
    const float* ab   = (const float*)d_in[18];
    const int*   bidx = (const int*)d_in[19];

    const int Bsz   = in_sizes[0] / (384 * 49);
    const int n_off = in_sizes[18] / 8;
    const size_t smem = (size_t)SM_FLOATS * sizeof(float);

    // pre-pass: transpose + tf32-round weights into device scratch
    const int tot = 384 * 640 + 512 * 384;
    transpose_w_kernel<<<(tot + 511) / 512, 512>>>(kw, vw, pw);

    cudaFuncSetAttribute(attn4dds_kernel,
                         cudaFuncAttributeMaxDynamicSharedMemorySize, (int)smem);

    attn4dds_kernel<<<Bsz, THREADS, smem>>>(
        x, qlw, qlb, qpw, qpb, qbn, kw, kb, kbn, vw, vb, vbn,
        vlw, vlb, vlbn, pw, pb, pbn, ab, bidx, n_off, (float*)d_out);
}

// round 9
// speedup vs baseline: 4.7952x; 1.0938x over previous
#include <cuda_runtime.h>
#include <math.h>
#include <stdint.h>

// Attention4DDownsample — fused, one CTA per image; big GEMMs via mma.sync tf32,
// A-fragments loaded directly from pre-transposed global weights (no staging,
// no mainloop barriers).

#define THREADS 640
#define NWARP   20
#define EPS     1e-5f
#define SCALE   0.25f

// ---- SMEM layout (float offsets) ----
#define OFF_XS    0        // xs[384][56] tf32-rounded, cols 49..55 zero   (21504)
#define XSS       56
#define OFF_ST    31872    // sT[16][390]                                  (6240)
#define SST       390
#define OFF_QO    51584    // qo[128][16]                                  (2048) -> 53632
// overlays after KV mma (xs dead):
#define OFF_KS    0        // k[128][51]
#define KSS       51
#define OFF_V     6528     // v[512][51]  -> 32640
#define OFF_PROBS 32640    // probs[128][52] -> 39296
#define PRS       52
#define OFF_PRE   39296    // pre[512][24]   -> 51584
#define PRES      24
#define SM_FLOATS 53632    // 214,528 bytes

// weight scratch (transposed, tf32-rounded) — static device arrays (no alloc)
__device__ float g_wT[384 * 640];    // [k][oc], oc<128 = K-branch, else V
__device__ float g_pwT[512 * 384];   // [k][oc]

__device__ __forceinline__ float totf32(float f) {
    uint32_t r;
    asm("cvt.rna.tf32.f32 %0, %1;" : "=r"(r) : "f"(f));
    return __uint_as_float(r);
}
__device__ __forceinline__ void mma8(float* d, uint32_t a0, uint32_t a1, uint32_t a2,
                                     uint32_t a3, uint32_t b0, uint32_t b1) {
    asm("mma.sync.aligned.m16n8k8.row.col.f32.tf32.tf32.f32 "
        "{%0,%1,%2,%3}, {%4,%5,%6,%7}, {%8,%9}, {%0,%1,%2,%3};"
        : "+f"(d[0]), "+f"(d[1]), "+f"(d[2]), "+f"(d[3])
        : "r"(a0), "r"(a1), "r"(a2), "r"(a3), "r"(b0), "r"(b1));
}
typedef unsigned long long ull;
__device__ __forceinline__ ull fma2(ull a, ull b, ull c) {
    ull d;
    asm("fma.rn.f32x2 %0, %1, %2, %3;" : "=l"(d) : "l"(a), "l"(b), "l"(c));
    return d;
}
__device__ __forceinline__ float psum(ull v) {
    float a, b;
    asm("mov.b64 {%0,%1}, %2;" : "=f"(a), "=f"(b) : "l"(v));
    return a + b;
}
__device__ __forceinline__ ull lds_u64(const float* p) { return *(const ull*)p; }

// ---- pre-pass: transpose + tf32-round weights ----
__global__ void transpose_w_kernel(const float* __restrict__ kw,
                                   const float* __restrict__ vw,
                                   const float* __restrict__ pw) {
    int i = blockIdx.x * blockDim.x + threadIdx.x;
    if (i < 384 * 640) {
        const int k = i / 640, oc = i % 640;
        const float v = (oc < 128) ? kw[oc * 384 + k] : vw[(oc - 128) * 384 + k];
        g_wT[i] = totf32(v);
    } else {
        const int j = i - 384 * 640;
        if (j < 512 * 384) {
            const int k = j / 384, oc = j % 384;
            g_pwT[j] = totf32(pw[oc * 512 + k]);
        }
    }
}

__global__ __launch_bounds__(THREADS, 1)
void attn4dds_kernel(
    const float* __restrict__ x,
    const float* __restrict__ qlw, const float* __restrict__ qlb,
    const float* __restrict__ qpw, const float* __restrict__ qpb, const float* __restrict__ qbn,
    const float* __restrict__ kw,  const float* __restrict__ kb,  const float* __restrict__ kbn,
    const float* __restrict__ vw,  const float* __restrict__ vb,  const float* __restrict__ vbn,
    const float* __restrict__ vlw, const float* __restrict__ vlb, const float* __restrict__ vlbn,
    const float* __restrict__ pw,  const float* __restrict__ pb,  const float* __restrict__ pbn,
    const float* __restrict__ ab,  const int* __restrict__ bidx_g, int n_off,
    float* __restrict__ out)
{
    extern __shared__ float sm[];
    const int tid  = threadIdx.x;
    const int lane = tid & 31;
    const int wid  = tid >> 5;
    const int b    = blockIdx.x;
    const int tq   = lane & 3;     // mma quad col (k index within fragment)
    const int tr   = lane >> 2;    // mma row-in-group

    // ---------- P1: stage x[b] -> xs[c][56] tf32, zero pad cols ----------
    {
        for (int i = tid; i < 384 * 7; i += THREADS)
            sm[OFF_XS + (i / 7) * XSS + 49 + (i % 7)] = 0.f;
        const float* xin = x + (size_t)b * 18816;
        for (int i = tid; i < 18816; i += THREADS) {
            const int c = i / 49, p = i - c * 49;
            sm[OFF_XS + c * XSS + p] = totf32(xin[i]);
        }
    }
    __syncthreads();

    // ---------- P2: sT[p][c] = dw3x3s2(x)+qlb + avgpool ----------
    if (tid < 384) {
        const int c = tid;
        const float* xc = sm + OFF_XS + c * XSS;
        float w9[9];
        #pragma unroll
        for (int i = 0; i < 9; i++) w9[i] = __ldg(&qlw[c * 9 + i]);
        const float bq = __ldg(&qlb[c]);
        #pragma unroll
        for (int i = 0; i < 4; i++) {
            #pragma unroll
            for (int j = 0; j < 4; j++) {
                float acc = bq;
                #pragma unroll
                for (int ki = 0; ki < 3; ki++) {
                    const int r = 2 * i - 1 + ki;
                    if (r < 0 || r > 6) continue;
                    #pragma unroll
                    for (int kj = 0; kj < 3; kj++) {
                        const int cl = 2 * j - 1 + kj;
                        if (cl < 0 || cl > 6) continue;
                        acc += w9[ki * 3 + kj] * xc[r * 7 + cl];
                    }
                }
                if (i < 3 && j < 3) {
                    acc += 0.25f * (xc[(2*i)*7 + 2*j]   + xc[(2*i)*7 + 2*j+1] +
                                    xc[(2*i+1)*7 + 2*j] + xc[(2*i+1)*7 + 2*j+1]);
                }
                sm[OFF_ST + (i * 4 + j) * SST + c] = acc;
            }
        }
    }
    __syncthreads();

    // ---------- P3: q GEMM (scalar fp32 FFMA2)  qo[128][16] ----------
    if (wid < 16) {
        const int p   = lane & 15;
        const int sub = lane >> 4;
        const int oc0 = wid * 8;
        ull acc[8];
        #pragma unroll
        for (int r = 0; r < 8; r++) acc[r] = 0ULL;
        #pragma unroll 2
        for (int c8 = 0; c8 < 48; c8++) {
            const int kofs = 8 * c8 + 4 * sub;
            const ull a0 = lds_u64(&sm[OFF_ST + p * SST + kofs]);
            const ull a1 = lds_u64(&sm[OFF_ST + p * SST + kofs + 2]);
            #pragma unroll
            for (int r = 0; r < 8; r++) {
                const ulonglong2 w = __ldg((const ulonglong2*)(qpw + (oc0 + r) * 384 + kofs));
                acc[r] = fma2(w.x, a0, acc[r]);
                acc[r] = fma2(w.y, a1, acc[r]);
            }
        }
        #pragma unroll
        for (int r = 0; r < 8; r++) {
            float s = psum(acc[r]);
            s += __shfl_xor_sync(0xffffffffu, s, 16);
            if (sub == 0) {
                const int oc = oc0 + r;
                const float ga = __ldg(&qbn[oc]),       be = __ldg(&qbn[128 + oc]);
                const float mn = __ldg(&qbn[256 + oc]), vr = __ldg(&qbn[384 + oc]);
                const float aa = ga * rsqrtf(vr + EPS);
                sm[OFF_QO + oc * 16 + p] = (s + __ldg(&qpb[oc])) * aa + (be - mn * aa);
            }
        }
    }
    __syncthreads();

    // ---------- P4: KV GEMM via mma.sync tf32 (A direct from g_wT) ----------
    float acc[2][7][4];
    #pragma unroll
    for (int j = 0; j < 2; j++)
        #pragma unroll
        for (int nt = 0; nt < 7; nt++)
            #pragma unroll
            for (int e = 0; e < 4; e++) acc[j][nt][e] = 0.f;
    {
        const int m0w = wid * 32;
        float pfA[8];
        #pragma unroll
        for (int j = 0; j < 2; j++) {
            const int m0 = m0w + j * 16;
            pfA[j*4+0] = __ldg(&g_wT[(tq)     * 640 + m0 + tr]);
            pfA[j*4+1] = __ldg(&g_wT[(tq)     * 640 + m0 + 8 + tr]);
            pfA[j*4+2] = __ldg(&g_wT[(4 + tq) * 640 + m0 + tr]);
            pfA[j*4+3] = __ldg(&g_wT[(4 + tq) * 640 + m0 + 8 + tr]);
        }
        #pragma unroll 1
        for (int ch = 0; ch < 48; ch++) {
            float a[8];
            #pragma unroll
            for (int i = 0; i < 8; i++) a[i] = pfA[i];
            if (ch < 47) {
                const int kg = (ch + 1) * 8;
                #pragma unroll
                for (int j = 0; j < 2; j++) {
                    const int m0 = m0w + j * 16;
                    pfA[j*4+0] = __ldg(&g_wT[(kg + tq)     * 640 + m0 + tr]);
                    pfA[j*4+1] = __ldg(&g_wT[(kg + tq)     * 640 + m0 + 8 + tr]);
                    pfA[j*4+2] = __ldg(&g_wT[(kg + 4 + tq) * 640 + m0 + tr]);
                    pfA[j*4+3] = __ldg(&g_wT[(kg + 4 + tq) * 640 + m0 + 8 + tr]);
                }
            }
            const int kg = ch * 8;
            uint32_t bf[7][2];
            #pragma unroll
            for (int nt = 0; nt < 7; nt++) {
                bf[nt][0] = __float_as_uint(sm[OFF_XS + (kg + tq) * XSS + nt * 8 + tr]);
                bf[nt][1] = __float_as_uint(sm[OFF_XS + (kg + 4 + tq) * XSS + nt * 8 + tr]);
            }
            #pragma unroll
            for (int j = 0; j < 2; j++) {
                const uint32_t a0 = __float_as_uint(a[j*4+0]);
                const uint32_t a1 = __float_as_uint(a[j*4+1]);
                const uint32_t a2 = __float_as_uint(a[j*4+2]);
                const uint32_t a3 = __float_as_uint(a[j*4+3]);
                #pragma unroll
                for (int nt = 0; nt < 7; nt++)
                    mma8(acc[j][nt], a0, a1, a2, a3, bf[nt][0], bf[nt][1]);
            }
        }
    }
    __syncthreads();   // all warps done reading xs before epilogue overlays it

    // ---- KV epilogue: BN + store k[128][51] / v[512][51] ----
    {
        #pragma unroll
        for (int j = 0; j < 2; j++) {
            const int mt = wid * 2 + j;
            #pragma unroll
            for (int rh = 0; rh < 2; rh++) {
                const int oc = mt * 16 + tr + rh * 8;
                float aa, sh, bs;
                float* dst;
                if (oc < 128) {
                    const float ga = __ldg(&kbn[oc]),       be = __ldg(&kbn[128 + oc]);
                    const float mn = __ldg(&kbn[256 + oc]), vr = __ldg(&kbn[384 + oc]);
                    aa = ga * rsqrtf(vr + EPS); sh = be - mn * aa; bs = __ldg(&kb[oc]);
                    dst = sm + OFF_KS + oc * KSS;
                } else {
                    const int vc = oc - 128;
                    const float ga = __ldg(&vbn[vc]),        be = __ldg(&vbn[512 + vc]);
                    const float mn = __ldg(&vbn[1024 + vc]), vr = __ldg(&vbn[1536 + vc]);
                    aa = ga * rsqrtf(vr + EPS); sh = be - mn * aa; bs = __ldg(&vb[vc]);
                    dst = sm + OFF_V + vc * KSS;
                }
                #pragma unroll
                for (int nt = 0; nt < 7; nt++) {
                    const int pos = nt * 8 + 2 * tq;
                    const float v0 = acc[j][nt][rh * 2 + 0];
                    const float v1 = acc[j][nt][rh * 2 + 1];
                    if (pos < 49)     dst[pos]     = (v0 + bs) * aa + sh;
                    if (pos + 1 < 49) dst[pos + 1] = (v1 + bs) * aa + sh;
                }
            }
        }
    }
    __syncthreads();

    // ---------- P5: attention scores + softmax -> probs[128][52] ----------
    {
        for (int row = wid; row < 128; row += NWARP) {
            const int h = row >> 4, q = row & 15;
            float qv[16];
            #pragma unroll
            for (int kd = 0; kd < 16; kd++) qv[kd] = sm[OFF_QO + (h * 16 + kd) * 16 + q];
            float a0 = 0.f, a1 = 0.f;
            #pragma unroll
            for (int kd = 0; kd < 16; kd++) {
                const float* kr = sm + OFF_KS + (h * 16 + kd) * KSS;
                a0 += qv[kd] * kr[lane];
                if (lane < 17) a1 += qv[kd] * kr[lane + 32];
            }
            a0 = a0 * SCALE + __ldg(&ab[h * n_off + __ldg(&bidx_g[q * 49 + lane])]);
            if (lane < 17) a1 = a1 * SCALE + __ldg(&ab[h * n_off + __ldg(&bidx_g[q * 49 + lane + 32])]);
            else           a1 = -1e30f;
            float m = fmaxf(a0, a1);
            #pragma unroll
            for (int o = 16; o > 0; o >>= 1) m = fmaxf(m, __shfl_xor_sync(0xffffffffu, m, o));
            const float e0 = __expf(a0 - m);
            const float e1 = (lane < 17) ? __expf(a1 - m) : 0.f;
            float ss = e0 + e1;
            #pragma unroll
            for (int o = 16; o > 0; o >>= 1) ss += __shfl_xor_sync(0xffffffffu, ss, o);
            const float inv = 1.f / ss;
            sm[OFF_PROBS + row * PRS + lane] = e0 * inv;
            if (lane < 17) sm[OFF_PROBS + row * PRS + lane + 32] = e1 * inv;
        }
    }
    __syncthreads();

    // ---------- P5b: pre[c][24] = tf32(relu(attn@v + BN(v_local))) ----------
    if (tid < 512) {
        const int c = tid;
        const int h = c >> 6;
        const float* vr_ = sm + OFF_V + c * KSS;
        float pacc[16];
        #pragma unroll
        for (int p = 0; p < 16; p++) pacc[p] = 0.f;
        #pragma unroll 2
        for (int k4 = 0; k4 < 12; k4++) {
            const float v0 = vr_[4 * k4 + 0];
            const float v1 = vr_[4 * k4 + 1];
            const float v2 = vr_[4 * k4 + 2];
            const float v3 = vr_[4 * k4 + 3];
            #pragma unroll
            for (int p = 0; p < 16; p++) {
                const float4 pr = *(const float4*)&sm[OFF_PROBS + (h * 16 + p) * PRS + 4 * k4];
                pacc[p] += pr.x * v0 + pr.y * v1 + pr.z * v2 + pr.w * v3;
            }
        }
        {
            const float v48 = vr_[48];
            #pragma unroll
            for (int p = 0; p < 16; p++)
                pacc[p] += sm[OFF_PROBS + (h * 16 + p) * PRS + 48] * v48;
        }
        float w9[9];
        #pragma unroll
        for (int i = 0; i < 9; i++) w9[i] = __ldg(&vlw[c * 9 + i]);
        const float bl = __ldg(&vlb[c]);
        const float ga = __ldg(&vlbn[c]),        be = __ldg(&vlbn[512 + c]);
        const float mn = __ldg(&vlbn[1024 + c]), vr2 = __ldg(&vlbn[1536 + c]);
        const float aa = ga * rsqrtf(vr2 + EPS);
        const float sh = be - mn * aa;
        #pragma unroll
        for (int i = 0; i < 4; i++) {
            #pragma unroll
            for (int j = 0; j < 4; j++) {
                float vl = bl;
                #pragma unroll
                for (int ki = 0; ki < 3; ki++) {
                    const int r = 2 * i - 1 + ki;
                    if (r < 0 || r > 6) continue;
                    #pragma unroll
                    for (int kj = 0; kj < 3; kj++) {
                        const int cl = 2 * j - 1 + kj;
                        if (cl < 0 || cl > 6) continue;
                        vl += w9[ki * 3 + kj] * vr_[r * 7 + cl];
                    }
                }
                sm[OFF_PRE + c * PRES + i * 4 + j] =
                    totf32(fmaxf(pacc[i * 4 + j] + vl * aa + sh, 0.f));
            }
        }
    }
    __syncthreads();

    // ---------- P6: proj GEMM via mma.sync tf32 (A direct from g_pwT) ----------
    if (wid < 12) {
        float acc2[2][2][4];
        #pragma unroll
        for (int j = 0; j < 2; j++)
            #pragma unroll
            for (int nt = 0; nt < 2; nt++)
                #pragma unroll
                for (int e = 0; e < 4; e++) acc2[j][nt][e] = 0.f;
        const int m0w = wid * 32;
        float pfA[8];
        #pragma unroll
        for (int j = 0; j < 2; j++) {
            const int m0 = m0w + j * 16;
            pfA[j*4+0] = __ldg(&g_pwT[(tq)     * 384 + m0 + tr]);
            pfA[j*4+1] = __ldg(&g_pwT[(tq)     * 384 + m0 + 8 + tr]);
            pfA[j*4+2] = __ldg(&g_pwT[(4 + tq) * 384 + m0 + tr]);
            pfA[j*4+3] = __ldg(&g_pwT[(4 + tq) * 384 + m0 + 8 + tr]);
        }
        #pragma unroll 1
        for (int ch = 0; ch < 64; ch++) {
            float a[8];
            #pragma unroll
            for (int i = 0; i < 8; i++) a[i] = pfA[i];
            if (ch < 63) {
                const int kg = (ch + 1) * 8;
                #pragma unroll
                for (int j = 0; j < 2; j++) {
                    const int m0 = m0w + j * 16;
                    pfA[j*4+0] = __ldg(&g_pwT[(kg + tq)     * 384 + m0 + tr]);
                    pfA[j*4+1] = __ldg(&g_pwT[(kg + tq)     * 384 + m0 + 8 + tr]);
                    pfA[j*4+2] = __ldg(&g_pwT[(kg + 4 + tq) * 384 + m0 + tr]);
                    pfA[j*4+3] = __ldg(&g_pwT[(kg + 4 + tq) * 384 + m0 + 8 + tr]);
                }
            }
            const int kg = ch * 8;
            uint32_t bf0[2], bf1[2];
            bf0[0] = __float_as_uint(sm[OFF_PRE + (kg + tq) * PRES + tr]);
            bf0[1] = __float_as_uint(sm[OFF_PRE + (kg + 4 + tq) * PRES + tr]);
            bf1[0] = __float_as_uint(sm[OFF_PRE + (kg + tq) * PRES + 8 + tr]);
            bf1[1] = __float_as_uint(sm[OFF_PRE + (kg + 4 + tq) * PRES + 8 + tr]);
            #pragma unroll
            for (int j = 0; j < 2; j++) {
                const uint32_t a0 = __float_as_uint(a[j*4+0]);
                const uint32_t a1 = __float_as_uint(a[j*4+1]);
                const uint32_t a2 = __float_as_uint(a[j*4+2]);
                const uint32_t a3 = __float_as_uint(a[j*4+3]);
                mma8(acc2[j][0], a0, a1, a2, a3, bf0[0], bf0[1]);
                mma8(acc2[j][1], a0, a1, a2, a3, bf1[0], bf1[1]);
            }
        }
        // proj epilogue: BN -> out
        float* ob = out + (size_t)b * 6144;
        #pragma unroll
        for (int j = 0; j < 2; j++) {
            const int mt = wid * 2 + j;
            #pragma unroll
            for (int rh = 0; rh < 2; rh++) {
                const int oc = mt * 16 + tr + rh * 8;
                const float ga = __ldg(&pbn[oc]),       be = __ldg(&pbn[384 + oc]);
                const float mn = __ldg(&pbn[768 + oc]), vr = __ldg(&pbn[1152 + oc]);
                const float aa = ga * rsqrtf(vr + EPS);
                const float sh = be - mn * aa, bs = __ldg(&pb[oc]);
                #pragma unroll
                for (int nt = 0; nt < 2; nt++) {
                    const int pos = nt * 8 + 2 * tq;
                    ob[oc * 16 + pos]     = (acc2[j][nt][rh * 2 + 0] + bs) * aa + sh;
                    ob[oc * 16 + pos + 1] = (acc2[j][nt][rh * 2 + 1] + bs) * aa + sh;
                }
            }
        }
    }
}

extern "C" void kernel_launch(void* const* d_in, const int* in_sizes, int n_in,
                              void* d_out, int out_size)
{
    const float* x    = (const float*)d_in[0];
    const float* qlw  = (const float*)d_in[1];
    const float* qlb  = (const float*)d_in[2];
    const float* qpw  = (const float*)d_in[3];
    const float* qpb  = (const float*)d_in[4];
    const float* qbn  = (const float*)d_in[5];
    const float* kw   = (const float*)d_in[6];
    const float* kb   = (const float*)d_in[7];
    const float* kbn  = (const float*)d_in[8];
    const float* vw   = (const float*)d_in[9];
    const float* vb   = (const float*)d_in[10];
    const float* vbn  = (const float*)d_in[11];
    const float* vlw  = (const float*)d_in[12];
    const float* vlb  = (const float*)d_in[13];
    const float* vlbn = (const float*)d_in[14];
    const float* pw   = (const float*)d_in[15];
    const float* pb   = (const float*)d_in[16];
    const float* pbn  = (const float*)d_in[17];
    const float* ab   = (const float*)d_in[18];
    const int*   bidx = (const int*)d_in[19];

    const int Bsz   = in_sizes[0] / (384 * 49);
    const int n_off = in_sizes[18] / 8;
    const size_t smem = (size_t)SM_FLOATS * sizeof(float);

    // pre-pass: transpose + tf32-round weights into device scratch
    const int tot = 384 * 640 + 512 * 384;
    transpose_w_kernel<<<(tot + 511) / 512, 512>>>(kw, vw, pw);

    cudaFuncSetAttribute(attn4dds_kernel,
                         cudaFuncAttributeMaxDynamicSharedMemorySize, (int)smem);

    attn4dds_kernel<<<Bsz, THREADS, smem>>>(
        x, qlw, qlb, qpw, qpb, qbn, kw, kb, kbn, vw, vb, vbn,
        vlw, vlb, vlbn, pw, pb, pbn, ab, bidx, n_off, (float*)d_out);
}

// round 10
// speedup vs baseline: 6.5494x; 1.3658x over previous
#include <cuda_runtime.h>
#include <math.h>
#include <stdint.h>

// Attention4DDownsample — fused, one CTA per image; all three big GEMMs via
// mma.sync tf32 with A-fragments packed in fragment order in global scratch
// (one 32B contiguous chunk per thread per k-chunk -> 2x LDG.128).

#define THREADS 640
#define NWARP   20
#define EPS     1e-5f
#define SCALE   0.25f

// ---- SMEM layout (float offsets) ----
#define OFF_XS    0        // xs[384][56] tf32, cols 49..55 zero  (21504)
#define XSS       56
#define OFF_SB    21504    // sB[384][24] tf32 q-input            (9216) -> 30720
#define SBS       24
#define OFF_QO    32640    // qo[128][16]                         (2048) -> 34688
// overlays after KV mma (xs/sB dead):
#define OFF_KS    0        // k[128][51]                          (6528)
#define KSS       51
#define OFF_V     6528     // v[512][51]                          (26112) -> 32640
#define OFF_PROBS 34688    // probs[128][52]                      (6656)  -> 41344
#define PRS       52
#define OFF_PRE   41344    // pre[512][24]                        (12288) -> 53632
#define PRES      24
#define SM_FLOATS 53632    // 214,528 bytes

// fragment-packed weight scratch (static device arrays; no alloc)
__device__ float g_wfrag[48 * 20 * 32 * 8];   // KV:   245,760
__device__ float g_qwfrag[48 * 8 * 32 * 4];   // Q:     49,152
__device__ float g_pwfrag[64 * 12 * 32 * 8];  // proj: 196,608

__device__ __forceinline__ float totf32(float f) {
    uint32_t r;
    asm("cvt.rna.tf32.f32 %0, %1;" : "=r"(r) : "f"(f));
    return __uint_as_float(r);
}
__device__ __forceinline__ void mma8(float* d, uint32_t a0, uint32_t a1, uint32_t a2,
                                     uint32_t a3, uint32_t b0, uint32_t b1) {
    asm("mma.sync.aligned.m16n8k8.row.col.f32.tf32.tf32.f32 "
        "{%0,%1,%2,%3}, {%4,%5,%6,%7}, {%8,%9}, {%0,%1,%2,%3};"
        : "+f"(d[0]), "+f"(d[1]), "+f"(d[2]), "+f"(d[3])
        : "r"(a0), "r"(a1), "r"(a2), "r"(a3), "r"(b0), "r"(b1));
}

// ---- pre-pass: pack weights into mma-fragment order, tf32-rounded ----
// fragment map (per lane, tq=lane&3, tr=lane>>2):
//   sub0=(row tr,     k tq)   sub1=(row 8+tr,   k tq)
//   sub2=(row tr,   k 4+tq)   sub3=(row 8+tr, k 4+tq)
__global__ void pack_w_kernel(const float* __restrict__ kw, const float* __restrict__ vw,
                              const float* __restrict__ qpw, const float* __restrict__ pw) {
    const int i = blockIdx.x * blockDim.x + threadIdx.x;
    if (i < 245760) {                       // KV: [ch48][wid20][lane32][8]
        const int e = i & 7, lane = (i >> 3) & 31, t = i >> 8;
        const int wid = t % 20, ch = t / 20;
        const int tq = lane & 3, tr = lane >> 2;
        const int k = ch * 8 + tq + ((e & 2) ? 4 : 0);
        const int oc = wid * 32 + (e >> 2) * 16 + tr + ((e & 1) ? 8 : 0);
        const float v = (oc < 128) ? kw[oc * 384 + k] : vw[(oc - 128) * 384 + k];
        g_wfrag[i] = totf32(v);
    } else if (i < 294912) {                // Q: [ch48][mt8][lane32][4]
        const int j = i - 245760;
        const int e = j & 3, lane = (j >> 2) & 31, t = j >> 7;
        const int mt = t & 7, ch = t >> 3;
        const int tq = lane & 3, tr = lane >> 2;
        const int k = ch * 8 + tq + ((e & 2) ? 4 : 0);
        const int row = mt * 16 + tr + ((e & 1) ? 8 : 0);
        g_qwfrag[j] = totf32(qpw[row * 384 + k]);
    } else if (i < 491520) {                // proj: [ch64][wid12][lane32][8]
        const int j = i - 294912;
        const int e = j & 7, lane = (j >> 3) & 31, t = j >> 8;
        const int wid = t % 12, ch = t / 12;
        const int tq = lane & 3, tr = lane >> 2;
        const int k = ch * 8 + tq + ((e & 2) ? 4 : 0);
        const int oc = wid * 32 + (e >> 2) * 16 + tr + ((e & 1) ? 8 : 0);
        g_pwfrag[j] = totf32(pw[oc * 512 + k]);
    }
}

__global__ __launch_bounds__(THREADS, 1)
void attn4dds_kernel(
    const float* __restrict__ x,
    const float* __restrict__ qlw, const float* __restrict__ qlb,
    const float* __restrict__ qpw, const float* __restrict__ qpb, const float* __restrict__ qbn,
    const float* __restrict__ kw,  const float* __restrict__ kb,  const float* __restrict__ kbn,
    const float* __restrict__ vw,  const float* __restrict__ vb,  const float* __restrict__ vbn,
    const float* __restrict__ vlw, const float* __restrict__ vlb, const float* __restrict__ vlbn,
    const float* __restrict__ pw,  const float* __restrict__ pb,  const float* __restrict__ pbn,
    const float* __restrict__ ab,  const int* __restrict__ bidx_g, int n_off,
    float* __restrict__ out)
{
    extern __shared__ float sm[];
    const int tid  = threadIdx.x;
    const int lane = tid & 31;
    const int wid  = tid >> 5;
    const int b    = blockIdx.x;
    const int tq   = lane & 3;
    const int tr   = lane >> 2;

    // ---------- P1: stage x[b] -> xs[c][56] tf32, zero pad cols ----------
    {
        for (int i = tid; i < 384 * 7; i += THREADS)
            sm[OFF_XS + (i / 7) * XSS + 49 + (i % 7)] = 0.f;
        const float* xin = x + (size_t)b * 18816;
        for (int i = tid; i < 18816; i += THREADS) {
            const int c = i / 49, p = i - c * 49;
            sm[OFF_XS + c * XSS + p] = totf32(xin[i]);
        }
    }
    __syncthreads();

    // ---------- P2: s = dw3x3s2(x)+qlb + avgpool -> sB[c][24] (tf32) ----------
    if (tid < 384) {
        const int c = tid;
        const float* xc = sm + OFF_XS + c * XSS;
        float w9[9];
        #pragma unroll
        for (int i = 0; i < 9; i++) w9[i] = __ldg(&qlw[c * 9 + i]);
        const float bq = __ldg(&qlb[c]);
        #pragma unroll
        for (int i = 0; i < 4; i++) {
            #pragma unroll
            for (int j = 0; j < 4; j++) {
                float acc = bq;
                #pragma unroll
                for (int ki = 0; ki < 3; ki++) {
                    const int r = 2 * i - 1 + ki;
                    if (r < 0 || r > 6) continue;
                    #pragma unroll
                    for (int kj = 0; kj < 3; kj++) {
                        const int cl = 2 * j - 1 + kj;
                        if (cl < 0 || cl > 6) continue;
                        acc += w9[ki * 3 + kj] * xc[r * 7 + cl];
                    }
                }
                if (i < 3 && j < 3) {
                    acc += 0.25f * (xc[(2*i)*7 + 2*j]   + xc[(2*i)*7 + 2*j+1] +
                                    xc[(2*i+1)*7 + 2*j] + xc[(2*i+1)*7 + 2*j+1]);
                }
                sm[OFF_SB + c * SBS + i * 4 + j] = totf32(acc);
            }
        }
    }
    __syncthreads();

    // ---------- P3: q GEMM via mma.sync (16 warps; runs before KV mma) ----------
    if (wid < 16) {
        const int mt = wid >> 1, nh = wid & 1;
        float qa[4] = {0.f, 0.f, 0.f, 0.f};
        const float4* qptr = (const float4*)g_qwfrag + (mt * 32 + lane);
        float4 pf = __ldg(qptr);
        #pragma unroll 1
        for (int ch = 0; ch < 48; ch++) {
            const float4 a = pf;
            if (ch < 47) pf = __ldg(qptr + (ch + 1) * 256);
            const int kg = ch * 8;
            const uint32_t b0 = __float_as_uint(sm[OFF_SB + (kg + tq) * SBS + nh * 8 + tr]);
            const uint32_t b1 = __float_as_uint(sm[OFF_SB + (kg + 4 + tq) * SBS + nh * 8 + tr]);
            mma8(qa, __float_as_uint(a.x), __float_as_uint(a.y),
                     __float_as_uint(a.z), __float_as_uint(a.w), b0, b1);
        }
        #pragma unroll
        for (int rh = 0; rh < 2; rh++) {
            const int oc = mt * 16 + tr + rh * 8;
            const float ga = __ldg(&qbn[oc]),       be = __ldg(&qbn[128 + oc]);
            const float mn = __ldg(&qbn[256 + oc]), vr = __ldg(&qbn[384 + oc]);
            const float aa = ga * rsqrtf(vr + EPS);
            const float sh = be - mn * aa, bs = __ldg(&qpb[oc]);
            const int p0 = nh * 8 + 2 * tq;
            sm[OFF_QO + oc * 16 + p0]     = (qa[rh * 2 + 0] + bs) * aa + sh;
            sm[OFF_QO + oc * 16 + p0 + 1] = (qa[rh * 2 + 1] + bs) * aa + sh;
        }
    }

    // ---------- P4: KV GEMM via mma.sync (A fragments: 2x LDG.128/chunk) ----------
    float acc[2][7][4];
    #pragma unroll
    for (int j = 0; j < 2; j++)
        #pragma unroll
        for (int nt = 0; nt < 7; nt++)
            #pragma unroll
            for (int e = 0; e < 4; e++) acc[j][nt][e] = 0.f;
    {
        const float4* wptr = (const float4*)g_wfrag + (wid * 32 + lane) * 2;
        float4 pf0 = __ldg(wptr), pf1 = __ldg(wptr + 1);
        #pragma unroll 1
        for (int ch = 0; ch < 48; ch++) {
            const float4 a0v = pf0, a1v = pf1;
            if (ch < 47) {
                const float4* np = wptr + (ch + 1) * 1280;
                pf0 = __ldg(np);
                pf1 = __ldg(np + 1);
            }
            const int kg = ch * 8;
            uint32_t bf[7][2];
            #pragma unroll
            for (int nt = 0; nt < 7; nt++) {
                bf[nt][0] = __float_as_uint(sm[OFF_XS + (kg + tq) * XSS + nt * 8 + tr]);
                bf[nt][1] = __float_as_uint(sm[OFF_XS + (kg + 4 + tq) * XSS + nt * 8 + tr]);
            }
            {
                const uint32_t a0 = __float_as_uint(a0v.x), a1 = __float_as_uint(a0v.y);
                const uint32_t a2 = __float_as_uint(a0v.z), a3 = __float_as_uint(a0v.w);
                #pragma unroll
                for (int nt = 0; nt < 7; nt++)
                    mma8(acc[0][nt], a0, a1, a2, a3, bf[nt][0], bf[nt][1]);
            }
            {
                const uint32_t a0 = __float_as_uint(a1v.x), a1 = __float_as_uint(a1v.y);
                const uint32_t a2 = __float_as_uint(a1v.z), a3 = __float_as_uint(a1v.w);
                #pragma unroll
                for (int nt = 0; nt < 7; nt++)
                    mma8(acc[1][nt], a0, a1, a2, a3, bf[nt][0], bf[nt][1]);
            }
        }
    }
    __syncthreads();   // all reads of xs/sB done before epilogue overlays them

    // ---- KV epilogue: BN + store k[128][51] / v[512][51] ----
    {
        #pragma unroll
        for (int j = 0; j < 2; j++) {
            const int mt = wid * 2 + j;
            #pragma unroll
            for (int rh = 0; rh < 2; rh++) {
                const int oc = mt * 16 + tr + rh * 8;
                float aa, sh, bs;
                float* dst;
                if (oc < 128) {
                    const float ga = __ldg(&kbn[oc]),       be = __ldg(&kbn[128 + oc]);
                    const float mn = __ldg(&kbn[256 + oc]), vr = __ldg(&kbn[384 + oc]);
                    aa = ga * rsqrtf(vr + EPS); sh = be - mn * aa; bs = __ldg(&kb[oc]);
                    dst = sm + OFF_KS + oc * KSS;
                } else {
                    const int vc = oc - 128;
                    const float ga = __ldg(&vbn[vc]),        be = __ldg(&vbn[512 + vc]);
                    const float mn = __ldg(&vbn[1024 + vc]), vr = __ldg(&vbn[1536 + vc]);
                    aa = ga * rsqrtf(vr + EPS); sh = be - mn * aa; bs = __ldg(&vb[vc]);
                    dst = sm + OFF_V + vc * KSS;
                }
                #pragma unroll
                for (int nt = 0; nt < 7; nt++) {
                    const int pos = nt * 8 + 2 * tq;
                    const float v0 = acc[j][nt][rh * 2 + 0];
                    const float v1 = acc[j][nt][rh * 2 + 1];
                    if (pos < 49)     dst[pos]     = (v0 + bs) * aa + sh;
                    if (pos + 1 < 49) dst[pos + 1] = (v1 + bs) * aa + sh;
                }
            }
        }
    }
    __syncthreads();

    // ---------- P5: attention scores + softmax -> probs[128][52] ----------
    {
        for (int row = wid; row < 128; row += NWARP) {
            const int h = row >> 4, q = row & 15;
            float qv[16];
            #pragma unroll
            for (int kd = 0; kd < 16; kd++) qv[kd] = sm[OFF_QO + (h * 16 + kd) * 16 + q];
            float a0 = 0.f, a1 = 0.f;
            #pragma unroll
            for (int kd = 0; kd < 16; kd++) {
                const float* kr = sm + OFF_KS + (h * 16 + kd) * KSS;
                a0 += qv[kd] * kr[lane];
                if (lane < 17) a1 += qv[kd] * kr[lane + 32];
            }
            a0 = a0 * SCALE + __ldg(&ab[h * n_off + __ldg(&bidx_g[q * 49 + lane])]);
            if (lane < 17) a1 = a1 * SCALE + __ldg(&ab[h * n_off + __ldg(&bidx_g[q * 49 + lane + 32])]);
            else           a1 = -1e30f;
            float m = fmaxf(a0, a1);
            #pragma unroll
            for (int o = 16; o > 0; o >>= 1) m = fmaxf(m, __shfl_xor_sync(0xffffffffu, m, o));
            const float e0 = __expf(a0 - m);
            const float e1 = (lane < 17) ? __expf(a1 - m) : 0.f;
            float ss = e0 + e1;
            #pragma unroll
            for (int o = 16; o > 0; o >>= 1) ss += __shfl_xor_sync(0xffffffffu, ss, o);
            const float inv = 1.f / ss;
            sm[OFF_PROBS + row * PRS + lane] = e0 * inv;
            if (lane < 17) sm[OFF_PROBS + row * PRS + lane + 32] = e1 * inv;
        }
    }
    __syncthreads();

    // ---------- P5b: pre[c][24] = tf32(relu(attn@v + BN(v_local))) ----------
    if (tid < 512) {
        const int c = tid;
        const int h = c >> 6;
        const float* vr_ = sm + OFF_V + c * KSS;
        float pacc[16];
        #pragma unroll
        for (int p = 0; p < 16; p++) pacc[p] = 0.f;
        #pragma unroll 2
        for (int k4 = 0; k4 < 12; k4++) {
            const float v0 = vr_[4 * k4 + 0];
            const float v1 = vr_[4 * k4 + 1];
            const float v2 = vr_[4 * k4 + 2];
            const float v3 = vr_[4 * k4 + 3];
            #pragma unroll
            for (int p = 0; p < 16; p++) {
                const float4 pr = *(const float4*)&sm[OFF_PROBS + (h * 16 + p) * PRS + 4 * k4];
                pacc[p] += pr.x * v0 + pr.y * v1 + pr.z * v2 + pr.w * v3;
            }
        }
        {
            const float v48 = vr_[48];
            #pragma unroll
            for (int p = 0; p < 16; p++)
                pacc[p] += sm[OFF_PROBS + (h * 16 + p) * PRS + 48] * v48;
        }
        float w9[9];
        #pragma unroll
        for (int i = 0; i < 9; i++) w9[i] = __ldg(&vlw[c * 9 + i]);
        const float bl = __ldg(&vlb[c]);
        const float ga = __ldg(&vlbn[c]),        be = __ldg(&vlbn[512 + c]);
        const float mn = __ldg(&vlbn[1024 + c]), vr2 = __ldg(&vlbn[1536 + c]);
        const float aa = ga * rsqrtf(vr2 + EPS);
        const float sh = be - mn * aa;
        #pragma unroll
        for (int i = 0; i < 4; i++) {
            #pragma unroll
            for (int j = 0; j < 4; j++) {
                float vl = bl;
                #pragma unroll
                for (int ki = 0; ki < 3; ki++) {
                    const int r = 2 * i - 1 + ki;
                    if (r < 0 || r > 6) continue;
                    #pragma unroll
                    for (int kj = 0; kj < 3; kj++) {
                        const int cl = 2 * j - 1 + kj;
                        if (cl < 0 || cl > 6) continue;
                        vl += w9[ki * 3 + kj] * vr_[r * 7 + cl];
                    }
                }
                sm[OFF_PRE + c * PRES + i * 4 + j] =
                    totf32(fmaxf(pacc[i * 4 + j] + vl * aa + sh, 0.f));
            }
        }
    }
    __syncthreads();

    // ---------- P6: proj GEMM via mma.sync (A fragments: 2x LDG.128/chunk) ----------
    if (wid < 12) {
        float acc2[2][2][4];
        #pragma unroll
        for (int j = 0; j < 2; j++)
            #pragma unroll
            for (int nt = 0; nt < 2; nt++)
                #pragma unroll
                for (int e = 0; e < 4; e++) acc2[j][nt][e] = 0.f;
        const float4* pptr = (const float4*)g_pwfrag + (wid * 32 + lane) * 2;
        float4 pf0 = __ldg(pptr), pf1 = __ldg(pptr + 1);
        #pragma unroll 1
        for (int ch = 0; ch < 64; ch++) {
            const float4 a0v = pf0, a1v = pf1;
            if (ch < 63) {
                const float4* np = pptr + (ch + 1) * 768;
                pf0 = __ldg(np);
                pf1 = __ldg(np + 1);
            }
            const int kg = ch * 8;
            uint32_t bf0[2], bf1[2];
            bf0[0] = __float_as_uint(sm[OFF_PRE + (kg + tq) * PRES + tr]);
            bf0[1] = __float_as_uint(sm[OFF_PRE + (kg + 4 + tq) * PRES + tr]);
            bf1[0] = __float_as_uint(sm[OFF_PRE + (kg + tq) * PRES + 8 + tr]);
            bf1[1] = __float_as_uint(sm[OFF_PRE + (kg + 4 + tq) * PRES + 8 + tr]);
            {
                const uint32_t a0 = __float_as_uint(a0v.x), a1 = __float_as_uint(a0v.y);
                const uint32_t a2 = __float_as_uint(a0v.z), a3 = __float_as_uint(a0v.w);
                mma8(acc2[0][0], a0, a1, a2, a3, bf0[0], bf0[1]);
                mma8(acc2[0][1], a0, a1, a2, a3, bf1[0], bf1[1]);
            }
            {
                const uint32_t a0 = __float_as_uint(a1v.x), a1 = __float_as_uint(a1v.y);
                const uint32_t a2 = __float_as_uint(a1v.z), a3 = __float_as_uint(a1v.w);
                mma8(acc2[1][0], a0, a1, a2, a3, bf0[0], bf0[1]);
                mma8(acc2[1][1], a0, a1, a2, a3, bf1[0], bf1[1]);
            }
        }
        // proj epilogue: BN -> out
        float* ob = out + (size_t)b * 6144;
        #pragma unroll
        for (int j = 0; j < 2; j++) {
            const int mt = wid * 2 + j;
            #pragma unroll
            for (int rh = 0; rh < 2; rh++) {
                const int oc = mt * 16 + tr + rh * 8;
                const float ga = __ldg(&pbn[oc]),       be = __ldg(&pbn[384 + oc]);
                const float mn = __ldg(&pbn[768 + oc]), vr = __ldg(&pbn[1152 + oc]);
                const float aa = ga * rsqrtf(vr + EPS);
                const float sh = be - mn * aa, bs = __ldg(&pb[oc]);
                #pragma unroll
                for (int nt = 0; nt < 2; nt++) {
                    const int pos = nt * 8 + 2 * tq;
                    ob[oc * 16 + pos]     = (acc2[j][nt][rh * 2 + 0] + bs) * aa + sh;
                    ob[oc * 16 + pos + 1] = (acc2[j][nt][rh * 2 + 1] + bs) * aa + sh;
                }
            }
        }
    }
}

extern "C" void kernel_launch(void* const* d_in, const int* in_sizes, int n_in,
                              void* d_out, int out_size)
{
    const float* x    = (const float*)d_in[0];
    const float* qlw  = (const float*)d_in[1];
    const float* qlb  = (const float*)d_in[2];
    const float* qpw  = (const float*)d_in[3];
    const float* qpb  = (const float*)d_in[4];
    const float* qbn  = (const float*)d_in[5];
    const float* kw   = (const float*)d_in[6];
    const float* kb   = (const float*)d_in[7];
    const float* kbn  = (const float*)d_in[8];
    const float* vw   = (const float*)d_in[9];
    const float* vb   = (const float*)d_in[10];
    const float* vbn  = (const float*)d_in[11];
    const float* vlw  = (const float*)d_in[12];
    const float* vlb  = (const float*)d_in[13];
    const float* vlbn = (const float*)d_in[14];
    const float* pw   = (const float*)d_in[15];
    const float* pb   = (const float*)d_in[16];
    const float* pbn  = (const float*)d_in[17];
    const float* ab   = (const float*)d_in[18];
    const int*   bidx = (const int*)d_in[19];

    const int Bsz   = in_sizes[0] / (384 * 49);
    const int n_off = in_sizes[18] / 8;
    const size_t smem = (size_t)SM_FLOATS * sizeof(float);

    // pre-pass: pack weights into fragment order (tf32-rounded)
    pack_w_kernel<<<(491520 + 511) / 512, 512>>>(kw, vw, qpw, pw);

    cudaFuncSetAttribute(attn4dds_kernel,
                         cudaFuncAttributeMaxDynamicSharedMemorySize, (int)smem);

    attn4dds_kernel<<<Bsz, THREADS, smem>>>(
        x, qlw, qlb, qpw, qpb, qbn, kw, kb, kbn, vw, vb, vbn,
        vlw, vlb, vlbn, pw, pb, pbn, ab, bidx, n_off, (float*)d_out);
}

// round 11
// speedup vs baseline: 6.8549x; 1.0466x over previous
#include <cuda_runtime.h>
#include <math.h>
#include <stdint.h>

// Attention4DDownsample — fused, one CTA per image; KV/Q/proj AND attn@v via
// mma.sync tf32. A-fragments for weight GEMMs packed in fragment order in
// global scratch (2x LDG.128 per chunk).

#define THREADS 640
#define NWARP   20
#define EPS     1e-5f
#define SCALE   0.25f

// ---- SMEM layout (float offsets) ----
#define OFF_XS    0        // xs[384][56] tf32, cols 49..55 zero  (21504)
#define XSS       56
#define OFF_SB    21504    // sB[384][24] tf32 q-input            (9216) -> 30720
#define SBS       24
// overlays after KV mma (xs/sB dead):
#define OFF_KS    0        // k[128][51]                          (6528)
#define KSS       51
#define OFF_V     6528     // v[512][52]                          (26624) -> 33152
#define VSS       52
#define OFF_QO    33152    // qo[128][16]                         (2048)  -> 35200
#define OFF_PROBS 35200    // probs[128][60], k-cols 49..55 zero  (7680)  -> 42880
#define PRS       60
#define OFF_PRE   42880    // pre[512][24]; cols 0..15 = xa/pre   (12288) -> 55168
#define PRES      24
#define SM_FLOATS 55168    // 220,672 bytes

// fragment-packed weight scratch (static device arrays; no alloc)
__device__ float g_wfrag[48 * 20 * 32 * 8];   // KV:   245,760
__device__ float g_qwfrag[48 * 8 * 32 * 4];   // Q:     49,152
__device__ float g_pwfrag[64 * 12 * 32 * 8];  // proj: 196,608

__device__ __forceinline__ float totf32(float f) {
    uint32_t r;
    asm("cvt.rna.tf32.f32 %0, %1;" : "=r"(r) : "f"(f));
    return __uint_as_float(r);
}
__device__ __forceinline__ void mma8(float* d, uint32_t a0, uint32_t a1, uint32_t a2,
                                     uint32_t a3, uint32_t b0, uint32_t b1) {
    asm("mma.sync.aligned.m16n8k8.row.col.f32.tf32.tf32.f32 "
        "{%0,%1,%2,%3}, {%4,%5,%6,%7}, {%8,%9}, {%0,%1,%2,%3};"
        : "+f"(d[0]), "+f"(d[1]), "+f"(d[2]), "+f"(d[3])
        : "r"(a0), "r"(a1), "r"(a2), "r"(a3), "r"(b0), "r"(b1));
}

// ---- pre-pass: pack weights into mma-fragment order, tf32-rounded ----
__global__ void pack_w_kernel(const float* __restrict__ kw, const float* __restrict__ vw,
                              const float* __restrict__ qpw, const float* __restrict__ pw) {
    const int i = blockIdx.x * blockDim.x + threadIdx.x;
    if (i < 245760) {                       // KV: [ch48][wid20][lane32][8]
        const int e = i & 7, lane = (i >> 3) & 31, t = i >> 8;
        const int wid = t % 20, ch = t / 20;
        const int tq = lane & 3, tr = lane >> 2;
        const int k = ch * 8 + tq + ((e & 2) ? 4 : 0);
        const int oc = wid * 32 + (e >> 2) * 16 + tr + ((e & 1) ? 8 : 0);
        const float v = (oc < 128) ? kw[oc * 384 + k] : vw[(oc - 128) * 384 + k];
        g_wfrag[i] = totf32(v);
    } else if (i < 294912) {                // Q: [ch48][mt8][lane32][4]
        const int j = i - 245760;
        const int e = j & 3, lane = (j >> 2) & 31, t = j >> 7;
        const int mt = t & 7, ch = t >> 3;
        const int tq = lane & 3, tr = lane >> 2;
        const int k = ch * 8 + tq + ((e & 2) ? 4 : 0);
        const int row = mt * 16 + tr + ((e & 1) ? 8 : 0);
        g_qwfrag[j] = totf32(qpw[row * 384 + k]);
    } else if (i < 491520) {                // proj: [ch64][wid12][lane32][8]
        const int j = i - 294912;
        const int e = j & 7, lane = (j >> 3) & 31, t = j >> 8;
        const int wid = t % 12, ch = t / 12;
        const int tq = lane & 3, tr = lane >> 2;
        const int k = ch * 8 + tq + ((e & 2) ? 4 : 0);
        const int oc = wid * 32 + (e >> 2) * 16 + tr + ((e & 1) ? 8 : 0);
        g_pwfrag[j] = totf32(pw[oc * 512 + k]);
    }
}

__global__ __launch_bounds__(THREADS, 1)
void attn4dds_kernel(
    const float* __restrict__ x,
    const float* __restrict__ qlw, const float* __restrict__ qlb,
    const float* __restrict__ qpw, const float* __restrict__ qpb, const float* __restrict__ qbn,
    const float* __restrict__ kw,  const float* __restrict__ kb,  const float* __restrict__ kbn,
    const float* __restrict__ vw,  const float* __restrict__ vb,  const float* __restrict__ vbn,
    const float* __restrict__ vlw, const float* __restrict__ vlb, const float* __restrict__ vlbn,
    const float* __restrict__ pw,  const float* __restrict__ pb,  const float* __restrict__ pbn,
    const float* __restrict__ ab,  const int* __restrict__ bidx_g, int n_off,
    float* __restrict__ out)
{
    extern __shared__ float sm[];
    const int tid  = threadIdx.x;
    const int lane = tid & 31;
    const int wid  = tid >> 5;
    const int b    = blockIdx.x;
    const int tq   = lane & 3;
    const int tr   = lane >> 2;

    // ---------- P1: stage x[b] -> xs[c][56] tf32, zero pad cols ----------
    {
        for (int i = tid; i < 384 * 7; i += THREADS)
            sm[OFF_XS + (i / 7) * XSS + 49 + (i % 7)] = 0.f;
        const float* xin = x + (size_t)b * 18816;
        for (int i = tid; i < 18816; i += THREADS) {
            const int c = i / 49, p = i - c * 49;
            sm[OFF_XS + c * XSS + p] = totf32(xin[i]);
        }
    }
    __syncthreads();

    // ---------- P2: s = dw3x3s2(x)+qlb + avgpool -> sB[c][24] (tf32) ----------
    if (tid < 384) {
        const int c = tid;
        const float* xc = sm + OFF_XS + c * XSS;
        float w9[9];
        #pragma unroll
        for (int i = 0; i < 9; i++) w9[i] = __ldg(&qlw[c * 9 + i]);
        const float bq = __ldg(&qlb[c]);
        #pragma unroll
        for (int i = 0; i < 4; i++) {
            #pragma unroll
            for (int j = 0; j < 4; j++) {
                float acc = bq;
                #pragma unroll
                for (int ki = 0; ki < 3; ki++) {
                    const int r = 2 * i - 1 + ki;
                    if (r < 0 || r > 6) continue;
                    #pragma unroll
                    for (int kj = 0; kj < 3; kj++) {
                        const int cl = 2 * j - 1 + kj;
                        if (cl < 0 || cl > 6) continue;
                        acc += w9[ki * 3 + kj] * xc[r * 7 + cl];
                    }
                }
                if (i < 3 && j < 3) {
                    acc += 0.25f * (xc[(2*i)*7 + 2*j]   + xc[(2*i)*7 + 2*j+1] +
                                    xc[(2*i+1)*7 + 2*j] + xc[(2*i+1)*7 + 2*j+1]);
                }
                sm[OFF_SB + c * SBS + i * 4 + j] = totf32(acc);
            }
        }
    }
    __syncthreads();

    // ---------- P3: q GEMM via mma.sync (16 warps) ----------
    if (wid < 16) {
        const int mt = wid >> 1, nh = wid & 1;
        float qa[4] = {0.f, 0.f, 0.f, 0.f};
        const float4* qptr = (const float4*)g_qwfrag + (mt * 32 + lane);
        float4 pf = __ldg(qptr);
        #pragma unroll 1
        for (int ch = 0; ch < 48; ch++) {
            const float4 a = pf;
            if (ch < 47) pf = __ldg(qptr + (ch + 1) * 256);
            const int kg = ch * 8;
            const uint32_t b0 = __float_as_uint(sm[OFF_SB + (kg + tq) * SBS + nh * 8 + tr]);
            const uint32_t b1 = __float_as_uint(sm[OFF_SB + (kg + 4 + tq) * SBS + nh * 8 + tr]);
            mma8(qa, __float_as_uint(a.x), __float_as_uint(a.y),
                     __float_as_uint(a.z), __float_as_uint(a.w), b0, b1);
        }
        #pragma unroll
        for (int rh = 0; rh < 2; rh++) {
            const int oc = mt * 16 + tr + rh * 8;
            const float ga = __ldg(&qbn[oc]),       be = __ldg(&qbn[128 + oc]);
            const float mn = __ldg(&qbn[256 + oc]), vr = __ldg(&qbn[384 + oc]);
            const float aa = ga * rsqrtf(vr + EPS);
            const float sh = be - mn * aa, bs = __ldg(&qpb[oc]);
            const int p0 = nh * 8 + 2 * tq;
            sm[OFF_QO + oc * 16 + p0]     = (qa[rh * 2 + 0] + bs) * aa + sh;
            sm[OFF_QO + oc * 16 + p0 + 1] = (qa[rh * 2 + 1] + bs) * aa + sh;
        }
    }

    // ---------- P4: KV GEMM via mma.sync (A fragments: 2x LDG.128/chunk) ----------
    float acc[2][7][4];
    #pragma unroll
    for (int j = 0; j < 2; j++)
        #pragma unroll
        for (int nt = 0; nt < 7; nt++)
            #pragma unroll
            for (int e = 0; e < 4; e++) acc[j][nt][e] = 0.f;
    {
        const float4* wptr = (const float4*)g_wfrag + (wid * 32 + lane) * 2;
        float4 pf0 = __ldg(wptr), pf1 = __ldg(wptr + 1);
        #pragma unroll 1
        for (int ch = 0; ch < 48; ch++) {
            const float4 a0v = pf0, a1v = pf1;
            if (ch < 47) {
                const float4* np = wptr + (ch + 1) * 1280;
                pf0 = __ldg(np);
                pf1 = __ldg(np + 1);
            }
            const int kg = ch * 8;
            uint32_t bf[7][2];
            #pragma unroll
            for (int nt = 0; nt < 7; nt++) {
                bf[nt][0] = __float_as_uint(sm[OFF_XS + (kg + tq) * XSS + nt * 8 + tr]);
                bf[nt][1] = __float_as_uint(sm[OFF_XS + (kg + 4 + tq) * XSS + nt * 8 + tr]);
            }
            {
                const uint32_t a0 = __float_as_uint(a0v.x), a1 = __float_as_uint(a0v.y);
                const uint32_t a2 = __float_as_uint(a0v.z), a3 = __float_as_uint(a0v.w);
                #pragma unroll
                for (int nt = 0; nt < 7; nt++)
                    mma8(acc[0][nt], a0, a1, a2, a3, bf[nt][0], bf[nt][1]);
            }
            {
                const uint32_t a0 = __float_as_uint(a1v.x), a1 = __float_as_uint(a1v.y);
                const uint32_t a2 = __float_as_uint(a1v.z), a3 = __float_as_uint(a1v.w);
                #pragma unroll
                for (int nt = 0; nt < 7; nt++)
                    mma8(acc[1][nt], a0, a1, a2, a3, bf[nt][0], bf[nt][1]);
            }
        }
    }
    __syncthreads();   // all reads of xs/sB done before epilogue overlays them

    // ---- KV epilogue: BN + store k[128][51] / v[512][52] ----
    {
        #pragma unroll
        for (int j = 0; j < 2; j++) {
            const int mt = wid * 2 + j;
            #pragma unroll
            for (int rh = 0; rh < 2; rh++) {
                const int oc = mt * 16 + tr + rh * 8;
                float aa, sh, bs;
                float* dst;
                if (oc < 128) {
                    const float ga = __ldg(&kbn[oc]),       be = __ldg(&kbn[128 + oc]);
                    const float mn = __ldg(&kbn[256 + oc]), vr = __ldg(&kbn[384 + oc]);
                    aa = ga * rsqrtf(vr + EPS); sh = be - mn * aa; bs = __ldg(&kb[oc]);
                    dst = sm + OFF_KS + oc * KSS;
                } else {
                    const int vc = oc - 128;
                    const float ga = __ldg(&vbn[vc]),        be = __ldg(&vbn[512 + vc]);
                    const float mn = __ldg(&vbn[1024 + vc]), vr = __ldg(&vbn[1536 + vc]);
                    aa = ga * rsqrtf(vr + EPS); sh = be - mn * aa; bs = __ldg(&vb[vc]);
                    dst = sm + OFF_V + vc * VSS;
                }
                #pragma unroll
                for (int nt = 0; nt < 7; nt++) {
                    const int pos = nt * 8 + 2 * tq;
                    const float v0 = acc[j][nt][rh * 2 + 0];
                    const float v1 = acc[j][nt][rh * 2 + 1];
                    if (pos < 49)     dst[pos]     = (v0 + bs) * aa + sh;
                    if (pos + 1 < 49) dst[pos + 1] = (v1 + bs) * aa + sh;
                }
            }
        }
    }
    __syncthreads();

    // ---------- P5: attention scores + softmax -> probs[128][60] ----------
    {
        for (int row = wid; row < 128; row += NWARP) {
            const int h = row >> 4, q = row & 15;
            float qv[16];
            #pragma unroll
            for (int kd = 0; kd < 16; kd++) qv[kd] = sm[OFF_QO + (h * 16 + kd) * 16 + q];
            float a0 = 0.f, a1 = 0.f;
            #pragma unroll
            for (int kd = 0; kd < 16; kd++) {
                const float* kr = sm + OFF_KS + (h * 16 + kd) * KSS;
                a0 += qv[kd] * kr[lane];
                if (lane < 17) a1 += qv[kd] * kr[lane + 32];
            }
            a0 = a0 * SCALE + __ldg(&ab[h * n_off + __ldg(&bidx_g[q * 49 + lane])]);
            if (lane < 17) a1 = a1 * SCALE + __ldg(&ab[h * n_off + __ldg(&bidx_g[q * 49 + lane + 32])]);
            else           a1 = -1e30f;
            float m = fmaxf(a0, a1);
            #pragma unroll
            for (int o = 16; o > 0; o >>= 1) m = fmaxf(m, __shfl_xor_sync(0xffffffffu, m, o));
            const float e0 = __expf(a0 - m);
            const float e1 = (lane < 17) ? __expf(a1 - m) : 0.f;
            float ss = e0 + e1;
            #pragma unroll
            for (int o = 16; o > 0; o >>= 1) ss += __shfl_xor_sync(0xffffffffu, ss, o);
            const float inv = 1.f / ss;
            sm[OFF_PROBS + row * PRS + lane] = e0 * inv;
            if (lane < 17)      sm[OFF_PROBS + row * PRS + lane + 32] = e1 * inv;
            else if (lane < 24) sm[OFF_PROBS + row * PRS + lane + 32] = 0.f;  // k-pad 49..55
        }
    }
    __syncthreads();

    // ---------- P5a: xa GEMM via mma.sync -> pre[c][0..15] ----------
    // per head h: D[64 d][16 p] = V[64][56] · P[16][56]^T ; warp w: channels 32w..32w+31
    if (wid < 16) {
        const int h = wid >> 1;
        float xacc[2][2][4];
        #pragma unroll
        for (int jm = 0; jm < 2; jm++)
            #pragma unroll
            for (int n = 0; n < 2; n++)
                #pragma unroll
                for (int e = 0; e < 4; e++) xacc[jm][n][e] = 0.f;
        #pragma unroll 1
        for (int ch = 0; ch < 7; ch++) {
            const int kg = ch * 8;
            uint32_t bf[2][2];
            #pragma unroll
            for (int n = 0; n < 2; n++) {
                const int prow = h * 16 + n * 8 + tr;
                bf[n][0] = __float_as_uint(sm[OFF_PROBS + prow * PRS + kg + tq]);
                bf[n][1] = __float_as_uint(sm[OFF_PROBS + prow * PRS + kg + 4 + tq]);
            }
            #pragma unroll
            for (int jm = 0; jm < 2; jm++) {
                const int m0 = wid * 32 + jm * 16;
                const uint32_t a0 = __float_as_uint(sm[OFF_V + (m0 + tr) * VSS + kg + tq]);
                const uint32_t a1 = __float_as_uint(sm[OFF_V + (m0 + 8 + tr) * VSS + kg + tq]);
                const uint32_t a2 = __float_as_uint(sm[OFF_V + (m0 + tr) * VSS + kg + 4 + tq]);
                const uint32_t a3 = __float_as_uint(sm[OFF_V + (m0 + 8 + tr) * VSS + kg + 4 + tq]);
                mma8(xacc[jm][0], a0, a1, a2, a3, bf[0][0], bf[0][1]);
                mma8(xacc[jm][1], a0, a1, a2, a3, bf[1][0], bf[1][1]);
            }
        }
        #pragma unroll
        for (int jm = 0; jm < 2; jm++)
            #pragma unroll
            for (int n = 0; n < 2; n++)
                #pragma unroll
                for (int rh = 0; rh < 2; rh++) {
                    const int c = wid * 32 + jm * 16 + tr + rh * 8;
                    const int p = n * 8 + 2 * tq;
                    sm[OFF_PRE + c * PRES + p]     = xacc[jm][n][rh * 2 + 0];
                    sm[OFF_PRE + c * PRES + p + 1] = xacc[jm][n][rh * 2 + 1];
                }
    }
    __syncthreads();

    // ---------- P5b: pre[c][p] = tf32(relu(xa + BN(v_local))) (in place) ----------
    if (tid < 512) {
        const int c = tid;
        const float* vr_ = sm + OFF_V + c * VSS;
        float w9[9];
        #pragma unroll
        for (int i = 0; i < 9; i++) w9[i] = __ldg(&vlw[c * 9 + i]);
        const float bl = __ldg(&vlb[c]);
        const float ga = __ldg(&vlbn[c]),        be = __ldg(&vlbn[512 + c]);
        const float mn = __ldg(&vlbn[1024 + c]), vr2 = __ldg(&vlbn[1536 + c]);
        const float aa = ga * rsqrtf(vr2 + EPS);
        const float sh = be - mn * aa;
        #pragma unroll
        for (int i = 0; i < 4; i++) {
            #pragma unroll
            for (int j = 0; j < 4; j++) {
                float vl = bl;
                #pragma unroll
                for (int ki = 0; ki < 3; ki++) {
                    const int r = 2 * i - 1 + ki;
                    if (r < 0 || r > 6) continue;
                    #pragma unroll
                    for (int kj = 0; kj < 3; kj++) {
                        const int cl = 2 * j - 1 + kj;
                        if (cl < 0 || cl > 6) continue;
                        vl += w9[ki * 3 + kj] * vr_[r * 7 + cl];
                    }
                }
                const int p = i * 4 + j;
                const float xa = sm[OFF_PRE + c * PRES + p];
                sm[OFF_PRE + c * PRES + p] = totf32(fmaxf(xa + vl * aa + sh, 0.f));
            }
        }
    }
    __syncthreads();

    // ---------- P6: proj GEMM via mma.sync (A fragments: 2x LDG.128/chunk) ----------
    if (wid < 12) {
        float acc2[2][2][4];
        #pragma unroll
        for (int j = 0; j < 2; j++)
            #pragma unroll
            for (int nt = 0; nt < 2; nt++)
                #pragma unroll
                for (int e = 0; e < 4; e++) acc2[j][nt][e] = 0.f;
        const float4* pptr = (const float4*)g_pwfrag + (wid * 32 + lane) * 2;
        float4 pf0 = __ldg(pptr), pf1 = __ldg(pptr + 1);
        #pragma unroll 1
        for (int ch = 0; ch < 64; ch++) {
            const float4 a0v = pf0, a1v = pf1;
            if (ch < 63) {
                const float4* np = pptr + (ch + 1) * 768;
                pf0 = __ldg(np);
                pf1 = __ldg(np + 1);
            }
            const int kg = ch * 8;
            uint32_t bf0[2], bf1[2];
            bf0[0] = __float_as_uint(sm[OFF_PRE + (kg + tq) * PRES + tr]);
            bf0[1] = __float_as_uint(sm[OFF_PRE + (kg + 4 + tq) * PRES + tr]);
            bf1[0] = __float_as_uint(sm[OFF_PRE + (kg + tq) * PRES + 8 + tr]);
            bf1[1] = __float_as_uint(sm[OFF_PRE + (kg + 4 + tq) * PRES + 8 + tr]);
            {
                const uint32_t a0 = __float_as_uint(a0v.x), a1 = __float_as_uint(a0v.y);
                const uint32_t a2 = __float_as_uint(a0v.z), a3 = __float_as_uint(a0v.w);
                mma8(acc2[0][0], a0, a1, a2, a3, bf0[0], bf0[1]);
                mma8(acc2[0][1], a0, a1, a2, a3, bf1[0], bf1[1]);
            }
            {
                const uint32_t a0 = __float_as_uint(a1v.x), a1 = __float_as_uint(a1v.y);
                const uint32_t a2 = __float_as_uint(a1v.z), a3 = __float_as_uint(a1v.w);
                mma8(acc2[1][0], a0, a1, a2, a3, bf0[0], bf0[1]);
                mma8(acc2[1][1], a0, a1, a2, a3, bf1[0], bf1[1]);
            }
        }
        // proj epilogue: BN -> out
        float* ob = out + (size_t)b * 6144;
        #pragma unroll
        for (int j = 0; j < 2; j++) {
            const int mt = wid * 2 + j;
            #pragma unroll
            for (int rh = 0; rh < 2; rh++) {
                const int oc = mt * 16 + tr + rh * 8;
                const float ga = __ldg(&pbn[oc]),       be = __ldg(&pbn[384 + oc]);
                const float mn = __ldg(&pbn[768 + oc]), vr = __ldg(&pbn[1152 + oc]);
                const float aa = ga * rsqrtf(vr + EPS);
                const float sh = be - mn * aa, bs = __ldg(&pb[oc]);
                #pragma unroll
                for (int nt = 0; nt < 2; nt++) {
                    const int pos = nt * 8 + 2 * tq;
                    ob[oc * 16 + pos]     = (acc2[j][nt][rh * 2 + 0] + bs) * aa + sh;
                    ob[oc * 16 + pos + 1] = (acc2[j][nt][rh * 2 + 1] + bs) * aa + sh;
                }
            }
        }
    }
}

extern "C" void kernel_launch(void* const* d_in, const int* in_sizes, int n_in,
                              void* d_out, int out_size)
{
    const float* x    = (const float*)d_in[0];
    const float* qlw  = (const float*)d_in[1];
    const float* qlb  = (const float*)d_in[2];
    const float* qpw  = (const float*)d_in[3];
    const float* qpb  = (const float*)d_in[4];
    const float* qbn  = (const float*)d_in[5];
    const float* kw   = (const float*)d_in[6];
    const float* kb   = (const float*)d_in[7];
    const float* kbn  = (const float*)d_in[8];
    const float* vw   = (const float*)d_in[9];
    const float* vb   = (const float*)d_in[10];
    const float* vbn  = (const float*)d_in[11];
    const float* vlw  = (const float*)d_in[12];
    const float* vlb  = (const float*)d_in[13];
    const float* vlbn = (const float*)d_in[14];
    const float* pw   = (const float*)d_in[15];
    const float* pb   = (const float*)d_in[16];
    const float* pbn  = (const float*)d_in[17];
    const float* ab   = (const float*)d_in[18];
    const int*   bidx = (const int*)d_in[19];

    const int Bsz   = in_sizes[0] / (384 * 49);
    const int n_off = in_sizes[18] / 8;
    const size_t smem = (size_t)SM_FLOATS * sizeof(float);

    // pre-pass: pack weights into fragment order (tf32-rounded)
    pack_w_kernel<<<(491520 + 511) / 512, 512>>>(kw, vw, qpw, pw);

    cudaFuncSetAttribute(attn4dds_kernel,
                         cudaFuncAttributeMaxDynamicSharedMemorySize, (int)smem);

    attn4dds_kernel<<<Bsz, THREADS, smem>>>(
        x, qlw, qlb, qpw, qpb, qbn, kw, kb, kbn, vw, vb, vbn,
        vlw, vlb, vlbn, pw, pb, pbn, ab, bidx, n_off, (float*)d_out);
}